// round 13
// baseline (speedup 1.0000x reference)
#include <cuda_runtime.h>
#include <cuda_bf16.h>
#include <cstdint>
#include <math.h>

// ---------------------------------------------------------------------------
// Model constants
// ---------------------------------------------------------------------------
#define N_LAYER 4
#define N_HEADS 16
#define C_DIM   1024
#define T_SEQ   1024
#define B_SZ    2
#define ROWS    (B_SZ * T_SEQ)      // 2048
#define F4_DIM  (4 * C_DIM)         // 4096
#define HEAD_D  64
#define VOCABP1 101
#define TRANS   16
#define K3C     (3 * C_DIM)         // 3072
#define K3F     (3 * F4_DIM)        // 12288
#define NQKV    (3 * C_DIM)         // 3072

// ---------------------------------------------------------------------------
// Static device scratch (no allocations allowed)
// ---------------------------------------------------------------------------
__device__ float g_x   [ROWS * C_DIM];
__device__ float g_h   [ROWS * C_DIM];
__device__ float g_qkv [ROWS * NQKV];
__device__ float g_part[2 * ROWS * C_DIM];            // split-K partials

__device__ __nv_bfloat16 g_aexpC[(size_t)ROWS * K3C];
__device__ __nv_bfloat16 g_aexpF[(size_t)ROWS * K3F];

__device__ __nv_bfloat16 g_wqkv[(size_t)N_LAYER * NQKV * K3C];
__device__ __nv_bfloat16 g_wp  [(size_t)N_LAYER * C_DIM * K3C];
__device__ __nv_bfloat16 g_w1  [(size_t)N_LAYER * F4_DIM * K3C];
__device__ __nv_bfloat16 g_w2  [(size_t)N_LAYER * C_DIM * K3F];

// ---------------------------------------------------------------------------
// PTX helpers (sm_80-safe only; ptxas targets plain sm_103)
// ---------------------------------------------------------------------------
__device__ __forceinline__ uint32_t smem_u32(const void* p) {
    uint32_t a;
    asm("{ .reg .u64 t; cvta.to.shared.u64 t, %1; cvt.u32.u64 %0, t; }" : "=r"(a) : "l"(p));
    return a;
}
__device__ __forceinline__ void cp_async16(uint32_t s, const void* g) {
    asm volatile("cp.async.cg.shared.global [%0], [%1], 16;" :: "r"(s), "l"(g));
}
__device__ __forceinline__ void cp_commit() { asm volatile("cp.async.commit_group;"); }
template<int N> __device__ __forceinline__ void cp_wait() {
    asm volatile("cp.async.wait_group %0;" :: "n"(N));
}
__device__ __forceinline__ void ldsm_x4(uint32_t& r0, uint32_t& r1, uint32_t& r2, uint32_t& r3,
                                        uint32_t addr) {
    asm volatile("ldmatrix.sync.aligned.m8n8.x4.shared.b16 {%0,%1,%2,%3}, [%4];"
                 : "=r"(r0), "=r"(r1), "=r"(r2), "=r"(r3) : "r"(addr));
}
__device__ __forceinline__ void mma16816(float* c, const uint32_t* a, uint32_t b0, uint32_t b1) {
    asm volatile("mma.sync.aligned.m16n8k16.row.col.f32.bf16.bf16.f32 "
                 "{%0,%1,%2,%3}, {%4,%5,%6,%7}, {%8,%9}, {%0,%1,%2,%3};"
                 : "+f"(c[0]), "+f"(c[1]), "+f"(c[2]), "+f"(c[3])
                 : "r"(a[0]), "r"(a[1]), "r"(a[2]), "r"(a[3]), "r"(b0), "r"(b1));
}
__device__ __forceinline__ uint32_t swz(int r, int s8) {
    return (uint32_t)(r * 128 + ((s8 ^ (r & 7)) << 4));
}

// ---------------------------------------------------------------------------
// Embedding
// ---------------------------------------------------------------------------
__global__ void embed_kernel(const int* __restrict__ tokens,
                             const float* __restrict__ tok_emb,
                             const float* __restrict__ pos_emb,
                             float* __restrict__ X)
{
    int i = blockIdx.x * blockDim.x + threadIdx.x;
    int row = i >> 10;
    int c   = i & 1023;
    int t   = row & 1023;
    int tok = tokens[row];
    X[i] = tok_emb[(size_t)tok * C_DIM + c] + pos_emb[(size_t)t * C_DIM + c];
}

// ---------------------------------------------------------------------------
// LayerNorm core (shared by ln_kernel / red_ln_kernel epilogues)
// EXP=0: fp32 Y. EXP=1: bf16 [hi|lo|hi] into Ye [row][3C]
// ---------------------------------------------------------------------------
template<int EXP>
__device__ __forceinline__ void ln_core(const float v[4], int row, int tid,
                                        const float* __restrict__ w,
                                        const float* __restrict__ b,
                                        float* __restrict__ Y,
                                        __nv_bfloat16* __restrict__ Ye)
{
    __shared__ float red[8];
    float s = v[0] + v[1] + v[2] + v[3];
#pragma unroll
    for (int off = 16; off; off >>= 1) s += __shfl_xor_sync(~0u, s, off);
    if ((tid & 31) == 0) red[tid >> 5] = s;
    __syncthreads();
    float tot = 0.f;
#pragma unroll
    for (int j = 0; j < 8; ++j) tot += red[j];
    const float mu = tot * (1.0f / C_DIM);
    __syncthreads();

    float ss = 0.f;
#pragma unroll
    for (int i = 0; i < 4; ++i) { float d = v[i] - mu; ss += d * d; }
#pragma unroll
    for (int off = 16; off; off >>= 1) ss += __shfl_xor_sync(~0u, ss, off);
    if ((tid & 31) == 0) red[tid >> 5] = ss;
    __syncthreads();
    float tot2 = 0.f;
#pragma unroll
    for (int j = 0; j < 8; ++j) tot2 += red[j];
    const float rs = rsqrtf(tot2 * (1.0f / C_DIM) + 1e-5f);

#pragma unroll
    for (int i = 0; i < 4; ++i) {
        const int c = tid + 256 * i;
        const float o = (v[i] - mu) * rs * w[c] + b[c];
        if (EXP == 0) {
            Y[(size_t)row * C_DIM + c] = o;
        } else {
            __nv_bfloat16 hi = __float2bfloat16(o);
            __nv_bfloat16 lo = __float2bfloat16(o - __bfloat162float(hi));
            __nv_bfloat16* yr = Ye + (size_t)row * K3C;
            yr[c]             = hi;
            yr[C_DIM + c]     = lo;
            yr[2 * C_DIM + c] = hi;
        }
    }
}

template<int EXP>
__global__ void ln_kernel(const float* __restrict__ X,
                          const float* __restrict__ w,
                          const float* __restrict__ b,
                          float* __restrict__ Y, __nv_bfloat16* __restrict__ Ye)
{
    const int row = blockIdx.x;
    const int tid = threadIdx.x;
    float v[4];
#pragma unroll
    for (int i = 0; i < 4; ++i) v[i] = X[(size_t)row * C_DIM + tid + 256 * i];
    ln_core<EXP>(v, row, tid, w, b, Y, Ye);
}

// ---------------------------------------------------------------------------
// Fused split-K reduce + residual update + LayerNorm:
// t = X + P0 + P1 + bias; X = t; LN(t) -> Y / Ye
// ---------------------------------------------------------------------------
template<int EXP>
__global__ void red_ln_kernel(const float* __restrict__ P,
                              const float* __restrict__ bias,
                              float* __restrict__ X,
                              const float* __restrict__ w,
                              const float* __restrict__ b,
                              float* __restrict__ Y, __nv_bfloat16* __restrict__ Ye)
{
    const int row = blockIdx.x;
    const int tid = threadIdx.x;
    const size_t base = (size_t)row * C_DIM;
    float v[4];
#pragma unroll
    for (int i = 0; i < 4; ++i) {
        const int c = tid + 256 * i;
        const float t = X[base + c] + P[base + c] + P[ROWS * C_DIM + base + c] + bias[c];
        X[base + c] = t;
        v[i] = t;
    }
    ln_core<EXP>(v, row, tid, w, b, Y, Ye);
}

// ---------------------------------------------------------------------------
// Split+transpose weight W [K,N] -> bf16 B' [N, 3K] = [hi | hi | lo]
// Batched over layers via blockIdx.z.
// ---------------------------------------------------------------------------
__global__ void expand_wT(const float* __restrict__ W, __nv_bfloat16* __restrict__ out,
                          int K, int N, size_t wstride, size_t ostride)
{
    W   += (size_t)blockIdx.z * wstride;
    out += (size_t)blockIdx.z * ostride;
    __shared__ float t[32][33];
    const int k0 = blockIdx.x * 32, n0 = blockIdx.y * 32;
    const int tx = threadIdx.x, ty = threadIdx.y;
#pragma unroll
    for (int i = 0; i < 4; ++i)
        t[ty + 8 * i][tx] = W[(size_t)(k0 + ty + 8 * i) * N + n0 + tx];
    __syncthreads();
#pragma unroll
    for (int i = 0; i < 4; ++i) {
        int n = n0 + ty + 8 * i;
        int k = k0 + tx;
        float x = t[tx][ty + 8 * i];
        __nv_bfloat16 hi = __float2bfloat16(x);
        __nv_bfloat16 lo = __float2bfloat16(x - __bfloat162float(hi));
        size_t base = (size_t)n * 3 * K;
        out[base + k]         = hi;
        out[base + K + k]     = hi;
        out[base + 2 * K + k] = lo;
    }
}

// Combined Q/K/V expansion: z in [0, 3*N_LAYER): mat = z%3, layer = z/3.
__global__ void expand_qkv(const float* __restrict__ Wq, const float* __restrict__ Wk,
                           const float* __restrict__ Wv, __nv_bfloat16* __restrict__ out)
{
    const int mat   = blockIdx.z % 3;
    const int layer = blockIdx.z / 3;
    const float* W = (mat == 0) ? Wq : (mat == 1) ? Wk : Wv;
    W   += (size_t)layer * C_DIM * C_DIM;
    out += (size_t)layer * NQKV * K3C + (size_t)mat * C_DIM * K3C;

    __shared__ float t[32][33];
    const int k0 = blockIdx.x * 32, n0 = blockIdx.y * 32;
    const int tx = threadIdx.x, ty = threadIdx.y;
#pragma unroll
    for (int i = 0; i < 4; ++i)
        t[ty + 8 * i][tx] = W[(size_t)(k0 + ty + 8 * i) * C_DIM + n0 + tx];
    __syncthreads();
#pragma unroll
    for (int i = 0; i < 4; ++i) {
        int n = n0 + ty + 8 * i;
        int k = k0 + tx;
        float x = t[tx][ty + 8 * i];
        __nv_bfloat16 hi = __float2bfloat16(x);
        __nv_bfloat16 lo = __float2bfloat16(x - __bfloat162float(hi));
        size_t base = (size_t)n * K3C;
        out[base + k]             = hi;
        out[base + C_DIM + k]     = hi;
        out[base + 2 * C_DIM + k] = lo;
    }
}

// ---------------------------------------------------------------------------
// HMMA bf16 GEMM: 128x128 tile, BK=64, 8 warps, 3-stage cp.async.
// Split-K via gridDim.z. EPI: 0 raw partial; 3 bias+gelu->Ce; 4 seg bias (q|k|v)
// ---------------------------------------------------------------------------
#define G_STAGES 3
#define G_TILEB  (128 * 128)
#define G_STAGEB (2 * G_TILEB)
#define G_SMEM   (G_STAGES * G_STAGEB)   // 98304

template<int EPI>
__global__ __launch_bounds__(256, 2)
void mma_gemm(const __nv_bfloat16* __restrict__ A, const __nv_bfloat16* __restrict__ B,
              const float* __restrict__ bias, const float* __restrict__ biasK,
              const float* __restrict__ biasV,
              float* __restrict__ Cf, __nv_bfloat16* __restrict__ Ce,
              int N, int Kfull, int Ksub)
{
    extern __shared__ char smem[];
    const uint32_t sbase = smem_u32(smem);
    const int tid  = threadIdx.x;
    const int wid  = tid >> 5, lane = tid & 31;
    const int warp_m = wid >> 2, warp_n = wid & 3;
    const int bx = blockIdx.x, by = blockIdx.y, bz = blockIdx.z;

    const char* Abase = (const char*)(A + (size_t)(by * 128) * Kfull + (size_t)bz * Ksub);
    const char* Bbase = (const char*)(B + (size_t)(bx * 128) * Kfull + (size_t)bz * Ksub);
    const size_t ldg = (size_t)Kfull * 2;
    const int nchunks = Ksub >> 6;

    const int r_cp[4] = { tid >> 3, (tid + 256) >> 3, (tid + 512) >> 3, (tid + 768) >> 3 };
    const int s8_cp   = tid & 7;

#pragma unroll
    for (int st = 0; st < G_STAGES - 1; ++st) {
        const uint32_t sb = sbase + st * G_STAGEB;
#pragma unroll
        for (int p = 0; p < 4; ++p) {
            const int r = r_cp[p];
            cp_async16(sb + swz(r, s8_cp),           Abase + (size_t)r * ldg + st * 128 + s8_cp * 16);
            cp_async16(sb + G_TILEB + swz(r, s8_cp), Bbase + (size_t)r * ldg + st * 128 + s8_cp * 16);
        }
        cp_commit();
    }

    float acc[4][4][4];
#pragma unroll
    for (int i = 0; i < 4; ++i)
#pragma unroll
        for (int j = 0; j < 4; ++j)
#pragma unroll
            for (int r = 0; r < 4; ++r) acc[i][j][r] = 0.f;

    const int a_r0 = warp_m * 64 + (lane & 15);
    const int a_s0 = lane >> 4;
    const int b_r0 = warp_n * 32 + (lane & 7) + ((lane >> 4) << 3);
    const int b_s0 = (lane >> 3) & 1;

    for (int c = 0; c < nchunks; ++c) {
        cp_wait<G_STAGES - 2>();
        __syncthreads();

        const int nc = c + G_STAGES - 1;
        if (nc < nchunks) {
            const uint32_t nb = sbase + (nc % G_STAGES) * G_STAGEB;
#pragma unroll
            for (int p = 0; p < 4; ++p) {
                const int r = r_cp[p];
                cp_async16(nb + swz(r, s8_cp),           Abase + (size_t)r * ldg + nc * 128 + s8_cp * 16);
                cp_async16(nb + G_TILEB + swz(r, s8_cp), Bbase + (size_t)r * ldg + nc * 128 + s8_cp * 16);
            }
        }
        cp_commit();

        const uint32_t sb = sbase + (c % G_STAGES) * G_STAGEB;
#pragma unroll
        for (int ks = 0; ks < 4; ++ks) {
            uint32_t af[4][4], bfr[2][4];
#pragma unroll
            for (int ma = 0; ma < 4; ++ma) {
                const int r = a_r0 + ma * 16;
                ldsm_x4(af[ma][0], af[ma][1], af[ma][2], af[ma][3],
                        sb + swz(r, ks * 2 + a_s0));
            }
#pragma unroll
            for (int j = 0; j < 2; ++j) {
                const int r = b_r0 + j * 16;
                ldsm_x4(bfr[j][0], bfr[j][1], bfr[j][2], bfr[j][3],
                        sb + G_TILEB + swz(r, ks * 2 + b_s0));
            }
#pragma unroll
            for (int ma = 0; ma < 4; ++ma)
#pragma unroll
                for (int na = 0; na < 4; ++na)
                    mma16816(acc[ma][na], af[ma], bfr[na >> 1][(na & 1) * 2],
                             bfr[na >> 1][(na & 1) * 2 + 1]);
        }
    }

    // epilogue
    float* Cout = (EPI == 0) ? (Cf + (size_t)bz * ROWS * N) : Cf;
#pragma unroll
    for (int ma = 0; ma < 4; ++ma) {
        const int row0 = by * 128 + warp_m * 64 + ma * 16 + (lane >> 2);
        const int row1 = row0 + 8;
#pragma unroll
        for (int na = 0; na < 4; ++na) {
            const int col = bx * 128 + warp_n * 32 + na * 8 + (lane & 3) * 2;
            if (EPI == 0) {
                *reinterpret_cast<float2*>(Cout + (size_t)row0 * N + col) =
                    make_float2(acc[ma][na][0], acc[ma][na][1]);
                *reinterpret_cast<float2*>(Cout + (size_t)row1 * N + col) =
                    make_float2(acc[ma][na][2], acc[ma][na][3]);
                continue;
            }
            float b0, b1;
            if (EPI == 4) {
                b0 = (col < C_DIM) ? bias[col]
                   : (col < 2 * C_DIM) ? biasK[col - C_DIM] : biasV[col - 2 * C_DIM];
                b1 = (col + 1 < C_DIM) ? bias[col + 1]
                   : (col + 1 < 2 * C_DIM) ? biasK[col + 1 - C_DIM] : biasV[col + 1 - 2 * C_DIM];
            } else {
                b0 = bias[col]; b1 = bias[col + 1];
            }
            float v0 = acc[ma][na][0] + b0;
            float v1 = acc[ma][na][1] + b1;
            float v2 = acc[ma][na][2] + b0;
            float v3 = acc[ma][na][3] + b1;
            if (EPI == 3) {
                v0 = 0.5f * v0 * (1.0f + erff(v0 * 0.70710678118654752f));
                v1 = 0.5f * v1 * (1.0f + erff(v1 * 0.70710678118654752f));
                v2 = 0.5f * v2 * (1.0f + erff(v2 * 0.70710678118654752f));
                v3 = 0.5f * v3 * (1.0f + erff(v3 * 0.70710678118654752f));
                __nv_bfloat162 h0, l0, h1, l1;
                h0.x = __float2bfloat16(v0); h0.y = __float2bfloat16(v1);
                l0.x = __float2bfloat16(v0 - __bfloat162float(h0.x));
                l0.y = __float2bfloat16(v1 - __bfloat162float(h0.y));
                h1.x = __float2bfloat16(v2); h1.y = __float2bfloat16(v3);
                l1.x = __float2bfloat16(v2 - __bfloat162float(h1.x));
                l1.y = __float2bfloat16(v3 - __bfloat162float(h1.y));
                __nv_bfloat16* c0 = Ce + (size_t)row0 * 3 * N;
                __nv_bfloat16* c1 = Ce + (size_t)row1 * 3 * N;
                *reinterpret_cast<__nv_bfloat162*>(c0 + col)         = h0;
                *reinterpret_cast<__nv_bfloat162*>(c0 + N + col)     = l0;
                *reinterpret_cast<__nv_bfloat162*>(c0 + 2 * N + col) = h0;
                *reinterpret_cast<__nv_bfloat162*>(c1 + col)         = h1;
                *reinterpret_cast<__nv_bfloat162*>(c1 + N + col)     = l1;
                *reinterpret_cast<__nv_bfloat162*>(c1 + 2 * N + col) = h1;
            } else {
                *reinterpret_cast<float2*>(Cout + (size_t)row0 * N + col) = make_float2(v0, v1);
                *reinterpret_cast<float2*>(Cout + (size_t)row1 * N + col) = make_float2(v2, v3);
            }
        }
    }
}

// ---------------------------------------------------------------------------
// Fused masked-causal attention, 4-way key batching, 8 queries/block
// (round-11 version — best measured).
// ---------------------------------------------------------------------------
__global__ __launch_bounds__(256)
void attn_kernel(const float* __restrict__ QKV, __nv_bfloat16* __restrict__ Ye)
{
    const int bh = blockIdx.x;
    const int b  = bh >> 4;
    const int h  = bh & 15;
    const int qbase = blockIdx.y * 8;
    const int warp = threadIdx.x >> 5;
    const int lane = threadIdx.x & 31;
    const int tq = qbase + warp;

    __shared__ float Ks[68][66];
    __shared__ float Vs[68][66];

    const size_t rq = (size_t)(b * T_SEQ + tq) * NQKV + h * HEAD_D;
    const float q0 = QKV[rq + lane * 2];
    const float q1 = QKV[rq + lane * 2 + 1];

    float m = -INFINITY, l = 0.f, acc0 = 0.f, acc1 = 0.f;
    const int smax = qbase + 7;

    for (int s0 = 0; s0 <= smax; s0 += 64) {
        const int tile = min(64, smax + 1 - s0);
        __syncthreads();
        for (int idx = threadIdx.x; idx < 68 * 64; idx += 256) {
            const int r = idx >> 6, cc = idx & 63;
            float kv = 0.f, vv = 0.f;
            if (r < tile) {
                const size_t g = (size_t)(b * T_SEQ + s0 + r) * NQKV + h * HEAD_D + cc;
                kv = QKV[g + C_DIM];
                vv = QKV[g + 2 * C_DIM];
            }
            Ks[r][cc] = kv; Vs[r][cc] = vv;
        }
        __syncthreads();

        const int rend = min(tq, s0 + 63) - s0;
        for (int r = 0; r <= rend; r += 4) {
            float p[4];
#pragma unroll
            for (int j = 0; j < 4; ++j)
                p[j] = q0 * Ks[r + j][lane * 2] + q1 * Ks[r + j][lane * 2 + 1];
#pragma unroll
            for (int off = 16; off; off >>= 1) {
#pragma unroll
                for (int j = 0; j < 4; ++j)
                    p[j] += __shfl_xor_sync(~0u, p[j], off);
            }
#pragma unroll
            for (int j = 0; j < 4; ++j) {
                const int s = s0 + r + j;
                const bool valid = (s <= tq) && ((s & 15) != 15);
                p[j] = valid ? p[j] * 0.125f : -INFINITY;
            }
            const float mnew = fmaxf(fmaxf(fmaxf(p[0], p[1]), fmaxf(p[2], p[3])), m);
            const float corr = __expf(m - mnew);
            const float w0 = __expf(p[0] - mnew);
            const float w1 = __expf(p[1] - mnew);
            const float w2 = __expf(p[2] - mnew);
            const float w3 = __expf(p[3] - mnew);
            l = l * corr + ((w0 + w1) + (w2 + w3));
            acc0 = acc0 * corr + w0 * Vs[r][lane * 2]     + w1 * Vs[r + 1][lane * 2]
                               + w2 * Vs[r + 2][lane * 2] + w3 * Vs[r + 3][lane * 2];
            acc1 = acc1 * corr + w0 * Vs[r][lane * 2 + 1]     + w1 * Vs[r + 1][lane * 2 + 1]
                               + w2 * Vs[r + 2][lane * 2 + 1] + w3 * Vs[r + 3][lane * 2 + 1];
            m = mnew;
        }
    }
    const float inv = 1.0f / l;
    const float o0 = acc0 * inv, o1 = acc1 * inv;

    const int row = b * T_SEQ + tq;
    const int c = h * HEAD_D + lane * 2;
    __nv_bfloat162 hi2, lo2;
    hi2.x = __float2bfloat16(o0); hi2.y = __float2bfloat16(o1);
    lo2.x = __float2bfloat16(o0 - __bfloat162float(hi2.x));
    lo2.y = __float2bfloat16(o1 - __bfloat162float(hi2.y));
    __nv_bfloat16* yr = Ye + (size_t)row * K3C;
    *reinterpret_cast<__nv_bfloat162*>(yr + c)             = hi2;
    *reinterpret_cast<__nv_bfloat162*>(yr + C_DIM + c)     = lo2;
    *reinterpret_cast<__nv_bfloat162*>(yr + 2 * C_DIM + c) = hi2;
}

// ---------------------------------------------------------------------------
// EinLinear head
// ---------------------------------------------------------------------------
__global__ __launch_bounds__(256)
void head_kernel(const float* __restrict__ X, const float* __restrict__ Wh,
                 float* __restrict__ out)
{
    const int e     = blockIdx.x & 15;
    const int chunk = blockIdx.x >> 4;
    const int tid = threadIdx.x;
    const int warp = tid >> 5, lane = tid & 31;

    __shared__ float xs[8][C_DIM];
    int rows[8];
#pragma unroll
    for (int j = 0; j < 8; ++j) rows[j] = (chunk * 8 + j) * TRANS + e;

#pragma unroll
    for (int j = 0; j < 8; ++j)
        for (int idx = tid; idx < C_DIM; idx += 256)
            xs[j][idx] = X[(size_t)rows[j] * C_DIM + idx];
    __syncthreads();

    for (int o = warp; o < VOCABP1; o += 8) {
        const float* w = Wh + ((size_t)e * VOCABP1 + o) * C_DIM;
        float a[8];
#pragma unroll
        for (int j = 0; j < 8; ++j) a[j] = 0.f;
        for (int k = lane; k < C_DIM; k += 32) {
            const float wv = w[k];
#pragma unroll
            for (int j = 0; j < 8; ++j) a[j] += wv * xs[j][k];
        }
#pragma unroll
        for (int j = 0; j < 8; ++j)
#pragma unroll
            for (int off = 16; off; off >>= 1)
                a[j] += __shfl_xor_sync(~0u, a[j], off);
        if (lane == 0) {
#pragma unroll
            for (int j = 0; j < 8; ++j)
                out[(size_t)rows[j] * VOCABP1 + o] = a[j];
        }
    }
}

// ---------------------------------------------------------------------------
// Launch. Order: expand_qkv(1), embed(2), ln1-l0(3), QKV GEMM(4) <- ncu slot.
// ---------------------------------------------------------------------------
extern "C" void kernel_launch(void* const* d_in, const int* in_sizes, int n_in,
                              void* d_out, int out_size)
{
    const int*   tokens  = (const int*)  d_in[0];
    const float* tok_emb = (const float*)d_in[1];
    const float* pos_emb = (const float*)d_in[2];
    const float* Wq = (const float*)d_in[3];  const float* bq = (const float*)d_in[4];
    const float* Wk = (const float*)d_in[5];  const float* bk = (const float*)d_in[6];
    const float* Wv = (const float*)d_in[7];  const float* bv = (const float*)d_in[8];
    const float* Wp = (const float*)d_in[9];  const float* bp = (const float*)d_in[10];
    const float* ln1w = (const float*)d_in[11]; const float* ln1b = (const float*)d_in[12];
    const float* ln2w = (const float*)d_in[13]; const float* ln2b = (const float*)d_in[14];
    const float* W1 = (const float*)d_in[15]; const float* b1 = (const float*)d_in[16];
    const float* W2 = (const float*)d_in[17]; const float* b2 = (const float*)d_in[18];
    const float* lnfw = (const float*)d_in[19]; const float* lnfb = (const float*)d_in[20];
    const float* head_w = (const float*)d_in[21];

    float *x, *h, *qkv, *part;
    __nv_bfloat16 *aC, *aF, *wqkvx, *wpx, *w1x, *w2x;
    cudaGetSymbolAddress((void**)&x,    g_x);
    cudaGetSymbolAddress((void**)&h,    g_h);
    cudaGetSymbolAddress((void**)&qkv,  g_qkv);
    cudaGetSymbolAddress((void**)&part, g_part);
    cudaGetSymbolAddress((void**)&aC,   g_aexpC);
    cudaGetSymbolAddress((void**)&aF,   g_aexpF);
    cudaGetSymbolAddress((void**)&wqkvx, g_wqkv);
    cudaGetSymbolAddress((void**)&wpx,  g_wp);
    cudaGetSymbolAddress((void**)&w1x,  g_w1);
    cudaGetSymbolAddress((void**)&w2x,  g_w2);

    cudaFuncSetAttribute(mma_gemm<0>, cudaFuncAttributeMaxDynamicSharedMemorySize, G_SMEM);
    cudaFuncSetAttribute(mma_gemm<3>, cudaFuncAttributeMaxDynamicSharedMemorySize, G_SMEM);
    cudaFuncSetAttribute(mma_gemm<4>, cudaFuncAttributeMaxDynamicSharedMemorySize, G_SMEM);

    const dim3 wb(32, 8);
    const dim3 gQKV(NQKV   / 128, ROWS / 128);        // (24, 16)
    const dim3 gF4 (F4_DIM / 128, ROWS / 128);        // (32, 16)
    const dim3 gCsp(C_DIM  / 128, ROWS / 128, 2);     // (8, 16, 2) split-K
    const dim3 gAtt(B_SZ * N_HEADS, T_SEQ / 8);       // (32, 128)

    // 1: all Q/K/V weight expansions (12 z-slices)
    expand_qkv<<<dim3(32, 32, 3 * N_LAYER), wb>>>(Wq, Wk, Wv, wqkvx);
    // 2: embedding
    embed_kernel<<<ROWS * C_DIM / 256, 256>>>(tokens, tok_emb, pos_emb, x);
    // 3: layer-0 ln1
    ln_kernel<1><<<ROWS, 256>>>(x, ln1w, ln1b, nullptr, aC);
    // 4: layer-0 QKV GEMM  <-- ncu profiles our 4th launch
    mma_gemm<4><<<gQKV, 256, G_SMEM>>>(aC, wqkvx, bq, bk, bv,
                                       qkv, nullptr, NQKV, K3C, K3C);

    // remaining weight expansions
    expand_wT<<<dim3(32, 32, N_LAYER), wb>>>(Wp, wpx,
        C_DIM, C_DIM, (size_t)C_DIM * C_DIM, (size_t)C_DIM * K3C);
    expand_wT<<<dim3(32, 128, N_LAYER), wb>>>(W1, w1x,
        C_DIM, F4_DIM, (size_t)C_DIM * F4_DIM, (size_t)F4_DIM * K3C);
    expand_wT<<<dim3(128, 32, N_LAYER), wb>>>(W2, w2x,
        F4_DIM, C_DIM, (size_t)F4_DIM * C_DIM, (size_t)C_DIM * K3F);

    for (int i = 0; i < N_LAYER; ++i) {
        const size_t bc = (size_t)i * C_DIM;

        if (i > 0) {
            mma_gemm<4><<<gQKV, 256, G_SMEM>>>(aC, wqkvx + (size_t)i * NQKV * K3C,
                                               bq + bc, bk + bc, bv + bc,
                                               qkv, nullptr, NQKV, K3C, K3C);
        }

        attn_kernel<<<gAtt, 256>>>(qkv, aC);

        // proj: split-K2 partials, then fused reduce+residual+ln2 -> aC
        mma_gemm<0><<<gCsp, 256, G_SMEM>>>(aC, wpx + (size_t)i * C_DIM * K3C,
                                           nullptr, nullptr, nullptr,
                                           part, nullptr, C_DIM, K3C, K3C / 2);
        red_ln_kernel<1><<<ROWS, 256>>>(part, bp + bc, x,
                                        ln2w + bc, ln2b + bc, nullptr, aC);

        mma_gemm<3><<<gF4, 256, G_SMEM>>>(aC, w1x + (size_t)i * F4_DIM * K3C,
                                          b1 + (size_t)i * F4_DIM, nullptr, nullptr,
                                          nullptr, aF, F4_DIM, K3C, K3C);

        // W2: split-K2 partials, then fused reduce+residual+(ln1_next | lnf)
        mma_gemm<0><<<gCsp, 256, G_SMEM>>>(aF, w2x + (size_t)i * C_DIM * K3F,
                                           nullptr, nullptr, nullptr,
                                           part, nullptr, C_DIM, K3F, K3F / 2);
        if (i < N_LAYER - 1) {
            red_ln_kernel<1><<<ROWS, 256>>>(part, b2 + bc, x,
                                            ln1w + bc + C_DIM, ln1b + bc + C_DIM,
                                            nullptr, aC);
        } else {
            red_ln_kernel<0><<<ROWS, 256>>>(part, b2 + bc, x,
                                            lnfw, lnfb, h, nullptr);
        }
    }

    head_kernel<<<256, 256>>>(h, head_w, (float*)d_out);
}

// round 14
// speedup vs baseline: 1.5837x; 1.5837x over previous
#include <cuda_runtime.h>
#include <cuda_bf16.h>
#include <cstdint>
#include <math.h>

// ---------------------------------------------------------------------------
// Model constants
// ---------------------------------------------------------------------------
#define N_LAYER 4
#define N_HEADS 16
#define C_DIM   1024
#define T_SEQ   1024
#define B_SZ    2
#define ROWS    (B_SZ * T_SEQ)      // 2048
#define F4_DIM  (4 * C_DIM)         // 4096
#define HEAD_D  64
#define VOCABP1 101
#define TRANS   16
#define K3C     (3 * C_DIM)         // 3072
#define K3F     (3 * F4_DIM)        // 12288
#define NQKV    (3 * C_DIM)         // 3072

// ---------------------------------------------------------------------------
// Static device scratch (no allocations allowed)
// ---------------------------------------------------------------------------
__device__ float g_x   [ROWS * C_DIM];
__device__ float g_h   [ROWS * C_DIM];
__device__ float g_qkv [ROWS * NQKV];
__device__ float g_part[2 * ROWS * C_DIM];            // split-K partials

__device__ __nv_bfloat16 g_aexpC[(size_t)ROWS * K3C];
__device__ __nv_bfloat16 g_aexpF[(size_t)ROWS * K3F];

__device__ __nv_bfloat16 g_wqkv[(size_t)N_LAYER * NQKV * K3C];
__device__ __nv_bfloat16 g_wp  [(size_t)N_LAYER * C_DIM * K3C];
__device__ __nv_bfloat16 g_w1  [(size_t)N_LAYER * F4_DIM * K3C];
__device__ __nv_bfloat16 g_w2  [(size_t)N_LAYER * C_DIM * K3F];

// ---------------------------------------------------------------------------
// PTX helpers (sm_80-safe only; ptxas targets plain sm_103)
// ---------------------------------------------------------------------------
__device__ __forceinline__ uint32_t smem_u32(const void* p) {
    uint32_t a;
    asm("{ .reg .u64 t; cvta.to.shared.u64 t, %1; cvt.u32.u64 %0, t; }" : "=r"(a) : "l"(p));
    return a;
}
__device__ __forceinline__ void cp_async16(uint32_t s, const void* g) {
    asm volatile("cp.async.cg.shared.global [%0], [%1], 16;" :: "r"(s), "l"(g));
}
__device__ __forceinline__ void cp_commit() { asm volatile("cp.async.commit_group;"); }
template<int N> __device__ __forceinline__ void cp_wait() {
    asm volatile("cp.async.wait_group %0;" :: "n"(N));
}
__device__ __forceinline__ void ldsm_x4(uint32_t& r0, uint32_t& r1, uint32_t& r2, uint32_t& r3,
                                        uint32_t addr) {
    asm volatile("ldmatrix.sync.aligned.m8n8.x4.shared.b16 {%0,%1,%2,%3}, [%4];"
                 : "=r"(r0), "=r"(r1), "=r"(r2), "=r"(r3) : "r"(addr));
}
__device__ __forceinline__ void mma16816(float* c, const uint32_t* a, uint32_t b0, uint32_t b1) {
    asm volatile("mma.sync.aligned.m16n8k16.row.col.f32.bf16.bf16.f32 "
                 "{%0,%1,%2,%3}, {%4,%5,%6,%7}, {%8,%9}, {%0,%1,%2,%3};"
                 : "+f"(c[0]), "+f"(c[1]), "+f"(c[2]), "+f"(c[3])
                 : "r"(a[0]), "r"(a[1]), "r"(a[2]), "r"(a[3]), "r"(b0), "r"(b1));
}
__device__ __forceinline__ uint32_t swz(int r, int s8) {
    return (uint32_t)(r * 128 + ((s8 ^ (r & 7)) << 4));
}

// ---------------------------------------------------------------------------
// Embedding
// ---------------------------------------------------------------------------
__global__ void embed_kernel(const int* __restrict__ tokens,
                             const float* __restrict__ tok_emb,
                             const float* __restrict__ pos_emb,
                             float* __restrict__ X)
{
    int i = blockIdx.x * blockDim.x + threadIdx.x;
    int row = i >> 10;
    int c   = i & 1023;
    int t   = row & 1023;
    int tok = tokens[row];
    X[i] = tok_emb[(size_t)tok * C_DIM + c] + pos_emb[(size_t)t * C_DIM + c];
}

// ---------------------------------------------------------------------------
// LayerNorm core (shared by ln_kernel / red_ln_kernel epilogues)
// EXP=0: fp32 Y. EXP=1: bf16 [hi|lo|hi] into Ye [row][3C]
// ---------------------------------------------------------------------------
template<int EXP>
__device__ __forceinline__ void ln_core(const float v[4], int row, int tid,
                                        const float* __restrict__ w,
                                        const float* __restrict__ b,
                                        float* __restrict__ Y,
                                        __nv_bfloat16* __restrict__ Ye)
{
    __shared__ float red[8];
    float s = v[0] + v[1] + v[2] + v[3];
#pragma unroll
    for (int off = 16; off; off >>= 1) s += __shfl_xor_sync(~0u, s, off);
    if ((tid & 31) == 0) red[tid >> 5] = s;
    __syncthreads();
    float tot = 0.f;
#pragma unroll
    for (int j = 0; j < 8; ++j) tot += red[j];
    const float mu = tot * (1.0f / C_DIM);
    __syncthreads();

    float ss = 0.f;
#pragma unroll
    for (int i = 0; i < 4; ++i) { float d = v[i] - mu; ss += d * d; }
#pragma unroll
    for (int off = 16; off; off >>= 1) ss += __shfl_xor_sync(~0u, ss, off);
    if ((tid & 31) == 0) red[tid >> 5] = ss;
    __syncthreads();
    float tot2 = 0.f;
#pragma unroll
    for (int j = 0; j < 8; ++j) tot2 += red[j];
    const float rs = rsqrtf(tot2 * (1.0f / C_DIM) + 1e-5f);

#pragma unroll
    for (int i = 0; i < 4; ++i) {
        const int c = tid + 256 * i;
        const float o = (v[i] - mu) * rs * w[c] + b[c];
        if (EXP == 0) {
            Y[(size_t)row * C_DIM + c] = o;
        } else {
            __nv_bfloat16 hi = __float2bfloat16(o);
            __nv_bfloat16 lo = __float2bfloat16(o - __bfloat162float(hi));
            __nv_bfloat16* yr = Ye + (size_t)row * K3C;
            yr[c]             = hi;
            yr[C_DIM + c]     = lo;
            yr[2 * C_DIM + c] = hi;
        }
    }
}

template<int EXP>
__global__ void ln_kernel(const float* __restrict__ X,
                          const float* __restrict__ w,
                          const float* __restrict__ b,
                          float* __restrict__ Y, __nv_bfloat16* __restrict__ Ye)
{
    const int row = blockIdx.x;
    const int tid = threadIdx.x;
    float v[4];
#pragma unroll
    for (int i = 0; i < 4; ++i) v[i] = X[(size_t)row * C_DIM + tid + 256 * i];
    ln_core<EXP>(v, row, tid, w, b, Y, Ye);
}

// ---------------------------------------------------------------------------
// Fused split-K reduce + residual update + LayerNorm:
// t = X + P0 + P1 + bias; X = t; LN(t) -> Y / Ye
// ---------------------------------------------------------------------------
template<int EXP>
__global__ void red_ln_kernel(const float* __restrict__ P,
                              const float* __restrict__ bias,
                              float* __restrict__ X,
                              const float* __restrict__ w,
                              const float* __restrict__ b,
                              float* __restrict__ Y, __nv_bfloat16* __restrict__ Ye)
{
    const int row = blockIdx.x;
    const int tid = threadIdx.x;
    const size_t base = (size_t)row * C_DIM;
    float v[4];
#pragma unroll
    for (int i = 0; i < 4; ++i) {
        const int c = tid + 256 * i;
        const float t = X[base + c] + P[base + c] + P[ROWS * C_DIM + base + c] + bias[c];
        X[base + c] = t;
        v[i] = t;
    }
    ln_core<EXP>(v, row, tid, w, b, Y, Ye);
}

// ---------------------------------------------------------------------------
// Split+transpose weight W [K,N] -> bf16 B' [N, 3K] = [hi | hi | lo]
// Batched over layers via blockIdx.z.
// ---------------------------------------------------------------------------
__global__ void expand_wT(const float* __restrict__ W, __nv_bfloat16* __restrict__ out,
                          int K, int N, size_t wstride, size_t ostride)
{
    W   += (size_t)blockIdx.z * wstride;
    out += (size_t)blockIdx.z * ostride;
    __shared__ float t[32][33];
    const int k0 = blockIdx.x * 32, n0 = blockIdx.y * 32;
    const int tx = threadIdx.x, ty = threadIdx.y;
#pragma unroll
    for (int i = 0; i < 4; ++i)
        t[ty + 8 * i][tx] = W[(size_t)(k0 + ty + 8 * i) * N + n0 + tx];
    __syncthreads();
#pragma unroll
    for (int i = 0; i < 4; ++i) {
        int n = n0 + ty + 8 * i;
        int k = k0 + tx;
        float x = t[tx][ty + 8 * i];
        __nv_bfloat16 hi = __float2bfloat16(x);
        __nv_bfloat16 lo = __float2bfloat16(x - __bfloat162float(hi));
        size_t base = (size_t)n * 3 * K;
        out[base + k]         = hi;
        out[base + K + k]     = hi;
        out[base + 2 * K + k] = lo;
    }
}

// Combined Q/K/V expansion: z in [0, 3*N_LAYER): mat = z%3, layer = z/3.
__global__ void expand_qkv(const float* __restrict__ Wq, const float* __restrict__ Wk,
                           const float* __restrict__ Wv, __nv_bfloat16* __restrict__ out)
{
    const int mat   = blockIdx.z % 3;
    const int layer = blockIdx.z / 3;
    const float* W = (mat == 0) ? Wq : (mat == 1) ? Wk : Wv;
    W   += (size_t)layer * C_DIM * C_DIM;
    out += (size_t)layer * NQKV * K3C + (size_t)mat * C_DIM * K3C;

    __shared__ float t[32][33];
    const int k0 = blockIdx.x * 32, n0 = blockIdx.y * 32;
    const int tx = threadIdx.x, ty = threadIdx.y;
#pragma unroll
    for (int i = 0; i < 4; ++i)
        t[ty + 8 * i][tx] = W[(size_t)(k0 + ty + 8 * i) * C_DIM + n0 + tx];
    __syncthreads();
#pragma unroll
    for (int i = 0; i < 4; ++i) {
        int n = n0 + ty + 8 * i;
        int k = k0 + tx;
        float x = t[tx][ty + 8 * i];
        __nv_bfloat16 hi = __float2bfloat16(x);
        __nv_bfloat16 lo = __float2bfloat16(x - __bfloat162float(hi));
        size_t base = (size_t)n * K3C;
        out[base + k]             = hi;
        out[base + C_DIM + k]     = hi;
        out[base + 2 * C_DIM + k] = lo;
    }
}

// ---------------------------------------------------------------------------
// HMMA bf16 GEMM: 128x128 tile, BK=64, 8 warps, 3-stage cp.async.
// Split-K via gridDim.z. EPI: 0 raw partial; 3 bias+gelu->Ce; 4 seg bias (q|k|v)
// ---------------------------------------------------------------------------
#define G_STAGES 3
#define G_TILEB  (128 * 128)
#define G_STAGEB (2 * G_TILEB)
#define G_SMEM   (G_STAGES * G_STAGEB)   // 98304

template<int EPI>
__global__ __launch_bounds__(256, 2)
void mma_gemm(const __nv_bfloat16* __restrict__ A, const __nv_bfloat16* __restrict__ B,
              const float* __restrict__ bias, const float* __restrict__ biasK,
              const float* __restrict__ biasV,
              float* __restrict__ Cf, __nv_bfloat16* __restrict__ Ce,
              int N, int Kfull, int Ksub)
{
    extern __shared__ char smem[];
    const uint32_t sbase = smem_u32(smem);
    const int tid  = threadIdx.x;
    const int wid  = tid >> 5, lane = tid & 31;
    const int warp_m = wid >> 2, warp_n = wid & 3;
    const int bx = blockIdx.x, by = blockIdx.y, bz = blockIdx.z;

    const char* Abase = (const char*)(A + (size_t)(by * 128) * Kfull + (size_t)bz * Ksub);
    const char* Bbase = (const char*)(B + (size_t)(bx * 128) * Kfull + (size_t)bz * Ksub);
    const size_t ldg = (size_t)Kfull * 2;
    const int nchunks = Ksub >> 6;

    const int r_cp[4] = { tid >> 3, (tid + 256) >> 3, (tid + 512) >> 3, (tid + 768) >> 3 };
    const int s8_cp   = tid & 7;

#pragma unroll
    for (int st = 0; st < G_STAGES - 1; ++st) {
        const uint32_t sb = sbase + st * G_STAGEB;
#pragma unroll
        for (int p = 0; p < 4; ++p) {
            const int r = r_cp[p];
            cp_async16(sb + swz(r, s8_cp),           Abase + (size_t)r * ldg + st * 128 + s8_cp * 16);
            cp_async16(sb + G_TILEB + swz(r, s8_cp), Bbase + (size_t)r * ldg + st * 128 + s8_cp * 16);
        }
        cp_commit();
    }

    float acc[4][4][4];
#pragma unroll
    for (int i = 0; i < 4; ++i)
#pragma unroll
        for (int j = 0; j < 4; ++j)
#pragma unroll
            for (int r = 0; r < 4; ++r) acc[i][j][r] = 0.f;

    const int a_r0 = warp_m * 64 + (lane & 15);
    const int a_s0 = lane >> 4;
    const int b_r0 = warp_n * 32 + (lane & 7) + ((lane >> 4) << 3);
    const int b_s0 = (lane >> 3) & 1;

    for (int c = 0; c < nchunks; ++c) {
        cp_wait<G_STAGES - 2>();
        __syncthreads();

        const int nc = c + G_STAGES - 1;
        if (nc < nchunks) {
            const uint32_t nb = sbase + (nc % G_STAGES) * G_STAGEB;
#pragma unroll
            for (int p = 0; p < 4; ++p) {
                const int r = r_cp[p];
                cp_async16(nb + swz(r, s8_cp),           Abase + (size_t)r * ldg + nc * 128 + s8_cp * 16);
                cp_async16(nb + G_TILEB + swz(r, s8_cp), Bbase + (size_t)r * ldg + nc * 128 + s8_cp * 16);
            }
        }
        cp_commit();

        const uint32_t sb = sbase + (c % G_STAGES) * G_STAGEB;
#pragma unroll
        for (int ks = 0; ks < 4; ++ks) {
            uint32_t af[4][4], bfr[2][4];
#pragma unroll
            for (int ma = 0; ma < 4; ++ma) {
                const int r = a_r0 + ma * 16;
                ldsm_x4(af[ma][0], af[ma][1], af[ma][2], af[ma][3],
                        sb + swz(r, ks * 2 + a_s0));
            }
#pragma unroll
            for (int j = 0; j < 2; ++j) {
                const int r = b_r0 + j * 16;
                ldsm_x4(bfr[j][0], bfr[j][1], bfr[j][2], bfr[j][3],
                        sb + G_TILEB + swz(r, ks * 2 + b_s0));
            }
#pragma unroll
            for (int ma = 0; ma < 4; ++ma)
#pragma unroll
                for (int na = 0; na < 4; ++na)
                    mma16816(acc[ma][na], af[ma], bfr[na >> 1][(na & 1) * 2],
                             bfr[na >> 1][(na & 1) * 2 + 1]);
        }
    }

    // epilogue
    float* Cout = (EPI == 0) ? (Cf + (size_t)bz * ROWS * N) : Cf;
#pragma unroll
    for (int ma = 0; ma < 4; ++ma) {
        const int row0 = by * 128 + warp_m * 64 + ma * 16 + (lane >> 2);
        const int row1 = row0 + 8;
#pragma unroll
        for (int na = 0; na < 4; ++na) {
            const int col = bx * 128 + warp_n * 32 + na * 8 + (lane & 3) * 2;
            if (EPI == 0) {
                *reinterpret_cast<float2*>(Cout + (size_t)row0 * N + col) =
                    make_float2(acc[ma][na][0], acc[ma][na][1]);
                *reinterpret_cast<float2*>(Cout + (size_t)row1 * N + col) =
                    make_float2(acc[ma][na][2], acc[ma][na][3]);
                continue;
            }
            float b0, b1;
            if (EPI == 4) {
                b0 = (col < C_DIM) ? bias[col]
                   : (col < 2 * C_DIM) ? biasK[col - C_DIM] : biasV[col - 2 * C_DIM];
                b1 = (col + 1 < C_DIM) ? bias[col + 1]
                   : (col + 1 < 2 * C_DIM) ? biasK[col + 1 - C_DIM] : biasV[col + 1 - 2 * C_DIM];
            } else {
                b0 = bias[col]; b1 = bias[col + 1];
            }
            float v0 = acc[ma][na][0] + b0;
            float v1 = acc[ma][na][1] + b1;
            float v2 = acc[ma][na][2] + b0;
            float v3 = acc[ma][na][3] + b1;
            if (EPI == 3) {
                v0 = 0.5f * v0 * (1.0f + erff(v0 * 0.70710678118654752f));
                v1 = 0.5f * v1 * (1.0f + erff(v1 * 0.70710678118654752f));
                v2 = 0.5f * v2 * (1.0f + erff(v2 * 0.70710678118654752f));
                v3 = 0.5f * v3 * (1.0f + erff(v3 * 0.70710678118654752f));
                __nv_bfloat162 h0, l0, h1, l1;
                h0.x = __float2bfloat16(v0); h0.y = __float2bfloat16(v1);
                l0.x = __float2bfloat16(v0 - __bfloat162float(h0.x));
                l0.y = __float2bfloat16(v1 - __bfloat162float(h0.y));
                h1.x = __float2bfloat16(v2); h1.y = __float2bfloat16(v3);
                l1.x = __float2bfloat16(v2 - __bfloat162float(h1.x));
                l1.y = __float2bfloat16(v3 - __bfloat162float(h1.y));
                __nv_bfloat16* c0 = Ce + (size_t)row0 * 3 * N;
                __nv_bfloat16* c1 = Ce + (size_t)row1 * 3 * N;
                *reinterpret_cast<__nv_bfloat162*>(c0 + col)         = h0;
                *reinterpret_cast<__nv_bfloat162*>(c0 + N + col)     = l0;
                *reinterpret_cast<__nv_bfloat162*>(c0 + 2 * N + col) = h0;
                *reinterpret_cast<__nv_bfloat162*>(c1 + col)         = h1;
                *reinterpret_cast<__nv_bfloat162*>(c1 + N + col)     = l1;
                *reinterpret_cast<__nv_bfloat162*>(c1 + 2 * N + col) = h1;
            } else {
                *reinterpret_cast<float2*>(Cout + (size_t)row0 * N + col) = make_float2(v0, v1);
                *reinterpret_cast<float2*>(Cout + (size_t)row1 * N + col) = make_float2(v2, v3);
            }
        }
    }
}

// ---------------------------------------------------------------------------
// Fused masked-causal attention, 4-way key batching, 8 queries/block
// (round-11 version — best measured).
// ---------------------------------------------------------------------------
__global__ __launch_bounds__(256)
void attn_kernel(const float* __restrict__ QKV, __nv_bfloat16* __restrict__ Ye)
{
    const int bh = blockIdx.x;
    const int b  = bh >> 4;
    const int h  = bh & 15;
    const int qbase = blockIdx.y * 8;
    const int warp = threadIdx.x >> 5;
    const int lane = threadIdx.x & 31;
    const int tq = qbase + warp;

    __shared__ float Ks[68][66];
    __shared__ float Vs[68][66];

    const size_t rq = (size_t)(b * T_SEQ + tq) * NQKV + h * HEAD_D;
    const float q0 = QKV[rq + lane * 2];
    const float q1 = QKV[rq + lane * 2 + 1];

    float m = -INFINITY, l = 0.f, acc0 = 0.f, acc1 = 0.f;
    const int smax = qbase + 7;

    for (int s0 = 0; s0 <= smax; s0 += 64) {
        const int tile = min(64, smax + 1 - s0);
        __syncthreads();
        for (int idx = threadIdx.x; idx < 68 * 64; idx += 256) {
            const int r = idx >> 6, cc = idx & 63;
            float kv = 0.f, vv = 0.f;
            if (r < tile) {
                const size_t g = (size_t)(b * T_SEQ + s0 + r) * NQKV + h * HEAD_D + cc;
                kv = QKV[g + C_DIM];
                vv = QKV[g + 2 * C_DIM];
            }
            Ks[r][cc] = kv; Vs[r][cc] = vv;
        }
        __syncthreads();

        const int rend = min(tq, s0 + 63) - s0;
        for (int r = 0; r <= rend; r += 4) {
            float p[4];
#pragma unroll
            for (int j = 0; j < 4; ++j)
                p[j] = q0 * Ks[r + j][lane * 2] + q1 * Ks[r + j][lane * 2 + 1];
#pragma unroll
            for (int off = 16; off; off >>= 1) {
#pragma unroll
                for (int j = 0; j < 4; ++j)
                    p[j] += __shfl_xor_sync(~0u, p[j], off);
            }
#pragma unroll
            for (int j = 0; j < 4; ++j) {
                const int s = s0 + r + j;
                const bool valid = (s <= tq) && ((s & 15) != 15);
                p[j] = valid ? p[j] * 0.125f : -INFINITY;
            }
            const float mnew = fmaxf(fmaxf(fmaxf(p[0], p[1]), fmaxf(p[2], p[3])), m);
            const float corr = __expf(m - mnew);
            const float w0 = __expf(p[0] - mnew);
            const float w1 = __expf(p[1] - mnew);
            const float w2 = __expf(p[2] - mnew);
            const float w3 = __expf(p[3] - mnew);
            l = l * corr + ((w0 + w1) + (w2 + w3));
            acc0 = acc0 * corr + w0 * Vs[r][lane * 2]     + w1 * Vs[r + 1][lane * 2]
                               + w2 * Vs[r + 2][lane * 2] + w3 * Vs[r + 3][lane * 2];
            acc1 = acc1 * corr + w0 * Vs[r][lane * 2 + 1]     + w1 * Vs[r + 1][lane * 2 + 1]
                               + w2 * Vs[r + 2][lane * 2 + 1] + w3 * Vs[r + 3][lane * 2 + 1];
            m = mnew;
        }
    }
    const float inv = 1.0f / l;
    const float o0 = acc0 * inv, o1 = acc1 * inv;

    const int row = b * T_SEQ + tq;
    const int c = h * HEAD_D + lane * 2;
    __nv_bfloat162 hi2, lo2;
    hi2.x = __float2bfloat16(o0); hi2.y = __float2bfloat16(o1);
    lo2.x = __float2bfloat16(o0 - __bfloat162float(hi2.x));
    lo2.y = __float2bfloat16(o1 - __bfloat162float(hi2.y));
    __nv_bfloat16* yr = Ye + (size_t)row * K3C;
    *reinterpret_cast<__nv_bfloat162*>(yr + c)             = hi2;
    *reinterpret_cast<__nv_bfloat162*>(yr + C_DIM + c)     = lo2;
    *reinterpret_cast<__nv_bfloat162*>(yr + 2 * C_DIM + c) = hi2;
}

// ---------------------------------------------------------------------------
// EinLinear head
// ---------------------------------------------------------------------------
__global__ __launch_bounds__(256)
void head_kernel(const float* __restrict__ X, const float* __restrict__ Wh,
                 float* __restrict__ out)
{
    const int e     = blockIdx.x & 15;
    const int chunk = blockIdx.x >> 4;
    const int tid = threadIdx.x;
    const int warp = tid >> 5, lane = tid & 31;

    __shared__ float xs[8][C_DIM];
    int rows[8];
#pragma unroll
    for (int j = 0; j < 8; ++j) rows[j] = (chunk * 8 + j) * TRANS + e;

#pragma unroll
    for (int j = 0; j < 8; ++j)
        for (int idx = tid; idx < C_DIM; idx += 256)
            xs[j][idx] = X[(size_t)rows[j] * C_DIM + idx];
    __syncthreads();

    for (int o = warp; o < VOCABP1; o += 8) {
        const float* w = Wh + ((size_t)e * VOCABP1 + o) * C_DIM;
        float a[8];
#pragma unroll
        for (int j = 0; j < 8; ++j) a[j] = 0.f;
        for (int k = lane; k < C_DIM; k += 32) {
            const float wv = w[k];
#pragma unroll
            for (int j = 0; j < 8; ++j) a[j] += wv * xs[j][k];
        }
#pragma unroll
        for (int j = 0; j < 8; ++j)
#pragma unroll
            for (int off = 16; off; off >>= 1)
                a[j] += __shfl_xor_sync(~0u, a[j], off);
        if (lane == 0) {
#pragma unroll
            for (int j = 0; j < 8; ++j)
                out[(size_t)rows[j] * VOCABP1 + o] = a[j];
        }
    }
}

// ---------------------------------------------------------------------------
// Launch. Order: expand_qkv(1), embed(2), ln1-l0(3), QKV GEMM(4) <- ncu slot.
// ---------------------------------------------------------------------------
extern "C" void kernel_launch(void* const* d_in, const int* in_sizes, int n_in,
                              void* d_out, int out_size)
{
    const int*   tokens  = (const int*)  d_in[0];
    const float* tok_emb = (const float*)d_in[1];
    const float* pos_emb = (const float*)d_in[2];
    const float* Wq = (const float*)d_in[3];  const float* bq = (const float*)d_in[4];
    const float* Wk = (const float*)d_in[5];  const float* bk = (const float*)d_in[6];
    const float* Wv = (const float*)d_in[7];  const float* bv = (const float*)d_in[8];
    const float* Wp = (const float*)d_in[9];  const float* bp = (const float*)d_in[10];
    const float* ln1w = (const float*)d_in[11]; const float* ln1b = (const float*)d_in[12];
    const float* ln2w = (const float*)d_in[13]; const float* ln2b = (const float*)d_in[14];
    const float* W1 = (const float*)d_in[15]; const float* b1 = (const float*)d_in[16];
    const float* W2 = (const float*)d_in[17]; const float* b2 = (const float*)d_in[18];
    const float* lnfw = (const float*)d_in[19]; const float* lnfb = (const float*)d_in[20];
    const float* head_w = (const float*)d_in[21];

    float *x, *h, *qkv, *part;
    __nv_bfloat16 *aC, *aF, *wqkvx, *wpx, *w1x, *w2x;
    cudaGetSymbolAddress((void**)&x,    g_x);
    cudaGetSymbolAddress((void**)&h,    g_h);
    cudaGetSymbolAddress((void**)&qkv,  g_qkv);
    cudaGetSymbolAddress((void**)&part, g_part);
    cudaGetSymbolAddress((void**)&aC,   g_aexpC);
    cudaGetSymbolAddress((void**)&aF,   g_aexpF);
    cudaGetSymbolAddress((void**)&wqkvx, g_wqkv);
    cudaGetSymbolAddress((void**)&wpx,  g_wp);
    cudaGetSymbolAddress((void**)&w1x,  g_w1);
    cudaGetSymbolAddress((void**)&w2x,  g_w2);

    cudaFuncSetAttribute(mma_gemm<0>, cudaFuncAttributeMaxDynamicSharedMemorySize, G_SMEM);
    cudaFuncSetAttribute(mma_gemm<3>, cudaFuncAttributeMaxDynamicSharedMemorySize, G_SMEM);
    cudaFuncSetAttribute(mma_gemm<4>, cudaFuncAttributeMaxDynamicSharedMemorySize, G_SMEM);

    const dim3 wb(32, 8);
    const dim3 gQKV(NQKV   / 128, ROWS / 128);        // (24, 16)
    const dim3 gF4 (F4_DIM / 128, ROWS / 128);        // (32, 16)
    const dim3 gCsp(C_DIM  / 128, ROWS / 128, 2);     // (8, 16, 2) split-K
    const dim3 gAtt(B_SZ * N_HEADS, T_SEQ / 8);       // (32, 128)

    // 1: all Q/K/V weight expansions (12 z-slices)
    expand_qkv<<<dim3(32, 32, 3 * N_LAYER), wb>>>(Wq, Wk, Wv, wqkvx);
    // 2: embedding
    embed_kernel<<<ROWS * C_DIM / 256, 256>>>(tokens, tok_emb, pos_emb, x);
    // 3: layer-0 ln1
    ln_kernel<1><<<ROWS, 256>>>(x, ln1w, ln1b, nullptr, aC);
    // 4: layer-0 QKV GEMM  <-- ncu profiles our 4th launch
    mma_gemm<4><<<gQKV, 256, G_SMEM>>>(aC, wqkvx, bq, bk, bv,
                                       qkv, nullptr, NQKV, K3C, K3C);

    // remaining weight expansions
    expand_wT<<<dim3(32, 32, N_LAYER), wb>>>(Wp, wpx,
        C_DIM, C_DIM, (size_t)C_DIM * C_DIM, (size_t)C_DIM * K3C);
    expand_wT<<<dim3(32, 128, N_LAYER), wb>>>(W1, w1x,
        C_DIM, F4_DIM, (size_t)C_DIM * F4_DIM, (size_t)F4_DIM * K3C);
    expand_wT<<<dim3(128, 32, N_LAYER), wb>>>(W2, w2x,
        F4_DIM, C_DIM, (size_t)F4_DIM * C_DIM, (size_t)C_DIM * K3F);

    for (int i = 0; i < N_LAYER; ++i) {
        const size_t bc = (size_t)i * C_DIM;

        if (i > 0) {
            mma_gemm<4><<<gQKV, 256, G_SMEM>>>(aC, wqkvx + (size_t)i * NQKV * K3C,
                                               bq + bc, bk + bc, bv + bc,
                                               qkv, nullptr, NQKV, K3C, K3C);
        }

        attn_kernel<<<gAtt, 256>>>(qkv, aC);

        // proj: split-K2 partials, then fused reduce+residual+ln2 -> aC
        mma_gemm<0><<<gCsp, 256, G_SMEM>>>(aC, wpx + (size_t)i * C_DIM * K3C,
                                           nullptr, nullptr, nullptr,
                                           part, nullptr, C_DIM, K3C, K3C / 2);
        red_ln_kernel<1><<<ROWS, 256>>>(part, bp + bc, x,
                                        ln2w + bc, ln2b + bc, nullptr, aC);

        mma_gemm<3><<<gF4, 256, G_SMEM>>>(aC, w1x + (size_t)i * F4_DIM * K3C,
                                          b1 + (size_t)i * F4_DIM, nullptr, nullptr,
                                          nullptr, aF, F4_DIM, K3C, K3C);

        // W2: split-K2 partials, then fused reduce+residual+(ln1_next | lnf)
        mma_gemm<0><<<gCsp, 256, G_SMEM>>>(aF, w2x + (size_t)i * C_DIM * K3F,
                                           nullptr, nullptr, nullptr,
                                           part, nullptr, C_DIM, K3F, K3F / 2);
        if (i < N_LAYER - 1) {
            red_ln_kernel<1><<<ROWS, 256>>>(part, b2 + bc, x,
                                            ln1w + bc + C_DIM, ln1b + bc + C_DIM,
                                            nullptr, aC);
        } else {
            red_ln_kernel<0><<<ROWS, 256>>>(part, b2 + bc, x,
                                            lnfw, lnfb, h, nullptr);
        }
    }

    head_kernel<<<256, 256>>>(h, head_w, (float*)d_out);
}

// round 15
// speedup vs baseline: 1.5859x; 1.0014x over previous
#include <cuda_runtime.h>
#include <cuda_bf16.h>
#include <cstdint>
#include <math.h>

// ---------------------------------------------------------------------------
// Model constants
// ---------------------------------------------------------------------------
#define N_LAYER 4
#define N_HEADS 16
#define C_DIM   1024
#define T_SEQ   1024
#define B_SZ    2
#define ROWS    (B_SZ * T_SEQ)      // 2048
#define F4_DIM  (4 * C_DIM)         // 4096
#define HEAD_D  64
#define VOCABP1 101
#define TRANS   16
#define K3C     (3 * C_DIM)         // 3072
#define K3F     (3 * F4_DIM)        // 12288
#define NQKV    (3 * C_DIM)         // 3072

// ---------------------------------------------------------------------------
// Static device scratch (no allocations allowed)
// ---------------------------------------------------------------------------
__device__ float g_x   [ROWS * C_DIM];
__device__ float g_h   [ROWS * C_DIM];
__device__ float g_qkv [ROWS * NQKV];
__device__ float g_part[2 * ROWS * C_DIM];            // split-K partials

__device__ __nv_bfloat16 g_aexpC[(size_t)ROWS * K3C];
__device__ __nv_bfloat16 g_aexpF[(size_t)ROWS * K3F];

__device__ __nv_bfloat16 g_wqkv[(size_t)N_LAYER * NQKV * K3C];
__device__ __nv_bfloat16 g_wp  [(size_t)N_LAYER * C_DIM * K3C];
__device__ __nv_bfloat16 g_w1  [(size_t)N_LAYER * F4_DIM * K3C];
__device__ __nv_bfloat16 g_w2  [(size_t)N_LAYER * C_DIM * K3F];

// ---------------------------------------------------------------------------
// PTX helpers (sm_80-safe only; ptxas targets plain sm_103)
// ---------------------------------------------------------------------------
__device__ __forceinline__ uint32_t smem_u32(const void* p) {
    uint32_t a;
    asm("{ .reg .u64 t; cvta.to.shared.u64 t, %1; cvt.u32.u64 %0, t; }" : "=r"(a) : "l"(p));
    return a;
}
__device__ __forceinline__ void cp_async16(uint32_t s, const void* g) {
    asm volatile("cp.async.cg.shared.global [%0], [%1], 16;" :: "r"(s), "l"(g));
}
__device__ __forceinline__ void cp_commit() { asm volatile("cp.async.commit_group;"); }
template<int N> __device__ __forceinline__ void cp_wait() {
    asm volatile("cp.async.wait_group %0;" :: "n"(N));
}
__device__ __forceinline__ void ldsm_x4(uint32_t& r0, uint32_t& r1, uint32_t& r2, uint32_t& r3,
                                        uint32_t addr) {
    asm volatile("ldmatrix.sync.aligned.m8n8.x4.shared.b16 {%0,%1,%2,%3}, [%4];"
                 : "=r"(r0), "=r"(r1), "=r"(r2), "=r"(r3) : "r"(addr));
}
__device__ __forceinline__ void mma16816(float* c, const uint32_t* a, uint32_t b0, uint32_t b1) {
    asm volatile("mma.sync.aligned.m16n8k16.row.col.f32.bf16.bf16.f32 "
                 "{%0,%1,%2,%3}, {%4,%5,%6,%7}, {%8,%9}, {%0,%1,%2,%3};"
                 : "+f"(c[0]), "+f"(c[1]), "+f"(c[2]), "+f"(c[3])
                 : "r"(a[0]), "r"(a[1]), "r"(a[2]), "r"(a[3]), "r"(b0), "r"(b1));
}
__device__ __forceinline__ uint32_t swz(int r, int s8) {
    return (uint32_t)(r * 128 + ((s8 ^ (r & 7)) << 4));
}

// ---------------------------------------------------------------------------
// LayerNorm core. EXP=0: fp32 Y. EXP=1: bf16 [hi|lo|hi] into Ye [row][3C]
// ---------------------------------------------------------------------------
template<int EXP>
__device__ __forceinline__ void ln_core(const float v[4], int row, int tid,
                                        const float* __restrict__ w,
                                        const float* __restrict__ b,
                                        float* __restrict__ Y,
                                        __nv_bfloat16* __restrict__ Ye)
{
    __shared__ float red[8];
    float s = v[0] + v[1] + v[2] + v[3];
#pragma unroll
    for (int off = 16; off; off >>= 1) s += __shfl_xor_sync(~0u, s, off);
    if ((tid & 31) == 0) red[tid >> 5] = s;
    __syncthreads();
    float tot = 0.f;
#pragma unroll
    for (int j = 0; j < 8; ++j) tot += red[j];
    const float mu = tot * (1.0f / C_DIM);
    __syncthreads();

    float ss = 0.f;
#pragma unroll
    for (int i = 0; i < 4; ++i) { float d = v[i] - mu; ss += d * d; }
#pragma unroll
    for (int off = 16; off; off >>= 1) ss += __shfl_xor_sync(~0u, ss, off);
    if ((tid & 31) == 0) red[tid >> 5] = ss;
    __syncthreads();
    float tot2 = 0.f;
#pragma unroll
    for (int j = 0; j < 8; ++j) tot2 += red[j];
    const float rs = rsqrtf(tot2 * (1.0f / C_DIM) + 1e-5f);

#pragma unroll
    for (int i = 0; i < 4; ++i) {
        const int c = tid + 256 * i;
        const float o = (v[i] - mu) * rs * w[c] + b[c];
        if (EXP == 0) {
            Y[(size_t)row * C_DIM + c] = o;
        } else {
            __nv_bfloat16 hi = __float2bfloat16(o);
            __nv_bfloat16 lo = __float2bfloat16(o - __bfloat162float(hi));
            __nv_bfloat16* yr = Ye + (size_t)row * K3C;
            yr[c]             = hi;
            yr[C_DIM + c]     = lo;
            yr[2 * C_DIM + c] = hi;
        }
    }
}

// ---------------------------------------------------------------------------
// Fused embedding + layer-0 ln1: x = tok_emb[tok] + pos_emb; X = x; LN -> Ye
// ---------------------------------------------------------------------------
__global__ void embed_ln_kernel(const int* __restrict__ tokens,
                                const float* __restrict__ tok_emb,
                                const float* __restrict__ pos_emb,
                                const float* __restrict__ w,
                                const float* __restrict__ b,
                                float* __restrict__ X,
                                __nv_bfloat16* __restrict__ Ye)
{
    const int row = blockIdx.x;
    const int tid = threadIdx.x;
    const int t   = row & 1023;
    const int tok = tokens[row];
    float v[4];
#pragma unroll
    for (int i = 0; i < 4; ++i) {
        const int c = tid + 256 * i;
        const float o = tok_emb[(size_t)tok * C_DIM + c] + pos_emb[(size_t)t * C_DIM + c];
        X[(size_t)row * C_DIM + c] = o;
        v[i] = o;
    }
    ln_core<1>(v, row, tid, w, b, nullptr, Ye);
}

// ---------------------------------------------------------------------------
// Fused split-K reduce + residual update + LayerNorm:
// t = X + P0 + P1 + bias; X = t; LN(t) -> Y / Ye
// ---------------------------------------------------------------------------
template<int EXP>
__global__ void red_ln_kernel(const float* __restrict__ P,
                              const float* __restrict__ bias,
                              float* __restrict__ X,
                              const float* __restrict__ w,
                              const float* __restrict__ b,
                              float* __restrict__ Y, __nv_bfloat16* __restrict__ Ye)
{
    const int row = blockIdx.x;
    const int tid = threadIdx.x;
    const size_t base = (size_t)row * C_DIM;
    float v[4];
#pragma unroll
    for (int i = 0; i < 4; ++i) {
        const int c = tid + 256 * i;
        const float t = X[base + c] + P[base + c] + P[ROWS * C_DIM + base + c] + bias[c];
        X[base + c] = t;
        v[i] = t;
    }
    ln_core<EXP>(v, row, tid, w, b, Y, Ye);
}

// ---------------------------------------------------------------------------
// Split+transpose weight W [K,N] -> bf16 B' [N, 3K] = [hi | hi | lo]
// Batched over layers via blockIdx.z.
// ---------------------------------------------------------------------------
__global__ void expand_wT(const float* __restrict__ W, __nv_bfloat16* __restrict__ out,
                          int K, int N, size_t wstride, size_t ostride)
{
    W   += (size_t)blockIdx.z * wstride;
    out += (size_t)blockIdx.z * ostride;
    __shared__ float t[32][33];
    const int k0 = blockIdx.x * 32, n0 = blockIdx.y * 32;
    const int tx = threadIdx.x, ty = threadIdx.y;
#pragma unroll
    for (int i = 0; i < 4; ++i)
        t[ty + 8 * i][tx] = W[(size_t)(k0 + ty + 8 * i) * N + n0 + tx];
    __syncthreads();
#pragma unroll
    for (int i = 0; i < 4; ++i) {
        int n = n0 + ty + 8 * i;
        int k = k0 + tx;
        float x = t[tx][ty + 8 * i];
        __nv_bfloat16 hi = __float2bfloat16(x);
        __nv_bfloat16 lo = __float2bfloat16(x - __bfloat162float(hi));
        size_t base = (size_t)n * 3 * K;
        out[base + k]         = hi;
        out[base + K + k]     = hi;
        out[base + 2 * K + k] = lo;
    }
}

// Combined Q/K/V expansion: z in [0, 3*N_LAYER): mat = z%3, layer = z/3.
__global__ void expand_qkv(const float* __restrict__ Wq, const float* __restrict__ Wk,
                           const float* __restrict__ Wv, __nv_bfloat16* __restrict__ out)
{
    const int mat   = blockIdx.z % 3;
    const int layer = blockIdx.z / 3;
    const float* W = (mat == 0) ? Wq : (mat == 1) ? Wk : Wv;
    W   += (size_t)layer * C_DIM * C_DIM;
    out += (size_t)layer * NQKV * K3C + (size_t)mat * C_DIM * K3C;

    __shared__ float t[32][33];
    const int k0 = blockIdx.x * 32, n0 = blockIdx.y * 32;
    const int tx = threadIdx.x, ty = threadIdx.y;
#pragma unroll
    for (int i = 0; i < 4; ++i)
        t[ty + 8 * i][tx] = W[(size_t)(k0 + ty + 8 * i) * C_DIM + n0 + tx];
    __syncthreads();
#pragma unroll
    for (int i = 0; i < 4; ++i) {
        int n = n0 + ty + 8 * i;
        int k = k0 + tx;
        float x = t[tx][ty + 8 * i];
        __nv_bfloat16 hi = __float2bfloat16(x);
        __nv_bfloat16 lo = __float2bfloat16(x - __bfloat162float(hi));
        size_t base = (size_t)n * K3C;
        out[base + k]             = hi;
        out[base + C_DIM + k]     = hi;
        out[base + 2 * C_DIM + k] = lo;
    }
}

// ---------------------------------------------------------------------------
// HMMA bf16 GEMM: 128x128 tile, BK=64, 8 warps, 3-stage cp.async.
// Split-K via gridDim.z. EPI: 0 raw partial; 3 bias+gelu->Ce; 4 seg bias (q|k|v)
// ---------------------------------------------------------------------------
#define G_STAGES 3
#define G_TILEB  (128 * 128)
#define G_STAGEB (2 * G_TILEB)
#define G_SMEM   (G_STAGES * G_STAGEB)   // 98304

template<int EPI>
__global__ __launch_bounds__(256, 2)
void mma_gemm(const __nv_bfloat16* __restrict__ A, const __nv_bfloat16* __restrict__ B,
              const float* __restrict__ bias, const float* __restrict__ biasK,
              const float* __restrict__ biasV,
              float* __restrict__ Cf, __nv_bfloat16* __restrict__ Ce,
              int N, int Kfull, int Ksub)
{
    extern __shared__ char smem[];
    const uint32_t sbase = smem_u32(smem);
    const int tid  = threadIdx.x;
    const int wid  = tid >> 5, lane = tid & 31;
    const int warp_m = wid >> 2, warp_n = wid & 3;
    const int bx = blockIdx.x, by = blockIdx.y, bz = blockIdx.z;

    const char* Abase = (const char*)(A + (size_t)(by * 128) * Kfull + (size_t)bz * Ksub);
    const char* Bbase = (const char*)(B + (size_t)(bx * 128) * Kfull + (size_t)bz * Ksub);
    const size_t ldg = (size_t)Kfull * 2;
    const int nchunks = Ksub >> 6;

    const int r_cp[4] = { tid >> 3, (tid + 256) >> 3, (tid + 512) >> 3, (tid + 768) >> 3 };
    const int s8_cp   = tid & 7;

#pragma unroll
    for (int st = 0; st < G_STAGES - 1; ++st) {
        const uint32_t sb = sbase + st * G_STAGEB;
#pragma unroll
        for (int p = 0; p < 4; ++p) {
            const int r = r_cp[p];
            cp_async16(sb + swz(r, s8_cp),           Abase + (size_t)r * ldg + st * 128 + s8_cp * 16);
            cp_async16(sb + G_TILEB + swz(r, s8_cp), Bbase + (size_t)r * ldg + st * 128 + s8_cp * 16);
        }
        cp_commit();
    }

    float acc[4][4][4];
#pragma unroll
    for (int i = 0; i < 4; ++i)
#pragma unroll
        for (int j = 0; j < 4; ++j)
#pragma unroll
            for (int r = 0; r < 4; ++r) acc[i][j][r] = 0.f;

    const int a_r0 = warp_m * 64 + (lane & 15);
    const int a_s0 = lane >> 4;
    const int b_r0 = warp_n * 32 + (lane & 7) + ((lane >> 4) << 3);
    const int b_s0 = (lane >> 3) & 1;

    for (int c = 0; c < nchunks; ++c) {
        cp_wait<G_STAGES - 2>();
        __syncthreads();

        const int nc = c + G_STAGES - 1;
        if (nc < nchunks) {
            const uint32_t nb = sbase + (nc % G_STAGES) * G_STAGEB;
#pragma unroll
            for (int p = 0; p < 4; ++p) {
                const int r = r_cp[p];
                cp_async16(nb + swz(r, s8_cp),           Abase + (size_t)r * ldg + nc * 128 + s8_cp * 16);
                cp_async16(nb + G_TILEB + swz(r, s8_cp), Bbase + (size_t)r * ldg + nc * 128 + s8_cp * 16);
            }
        }
        cp_commit();

        const uint32_t sb = sbase + (c % G_STAGES) * G_STAGEB;
#pragma unroll
        for (int ks = 0; ks < 4; ++ks) {
            uint32_t af[4][4], bfr[2][4];
#pragma unroll
            for (int ma = 0; ma < 4; ++ma) {
                const int r = a_r0 + ma * 16;
                ldsm_x4(af[ma][0], af[ma][1], af[ma][2], af[ma][3],
                        sb + swz(r, ks * 2 + a_s0));
            }
#pragma unroll
            for (int j = 0; j < 2; ++j) {
                const int r = b_r0 + j * 16;
                ldsm_x4(bfr[j][0], bfr[j][1], bfr[j][2], bfr[j][3],
                        sb + G_TILEB + swz(r, ks * 2 + b_s0));
            }
#pragma unroll
            for (int ma = 0; ma < 4; ++ma)
#pragma unroll
                for (int na = 0; na < 4; ++na)
                    mma16816(acc[ma][na], af[ma], bfr[na >> 1][(na & 1) * 2],
                             bfr[na >> 1][(na & 1) * 2 + 1]);
        }
    }

    // epilogue
    float* Cout = (EPI == 0) ? (Cf + (size_t)bz * ROWS * N) : Cf;
#pragma unroll
    for (int ma = 0; ma < 4; ++ma) {
        const int row0 = by * 128 + warp_m * 64 + ma * 16 + (lane >> 2);
        const int row1 = row0 + 8;
#pragma unroll
        for (int na = 0; na < 4; ++na) {
            const int col = bx * 128 + warp_n * 32 + na * 8 + (lane & 3) * 2;
            if (EPI == 0) {
                *reinterpret_cast<float2*>(Cout + (size_t)row0 * N + col) =
                    make_float2(acc[ma][na][0], acc[ma][na][1]);
                *reinterpret_cast<float2*>(Cout + (size_t)row1 * N + col) =
                    make_float2(acc[ma][na][2], acc[ma][na][3]);
                continue;
            }
            float b0, b1;
            if (EPI == 4) {
                b0 = (col < C_DIM) ? bias[col]
                   : (col < 2 * C_DIM) ? biasK[col - C_DIM] : biasV[col - 2 * C_DIM];
                b1 = (col + 1 < C_DIM) ? bias[col + 1]
                   : (col + 1 < 2 * C_DIM) ? biasK[col + 1 - C_DIM] : biasV[col + 1 - 2 * C_DIM];
            } else {
                b0 = bias[col]; b1 = bias[col + 1];
            }
            float v0 = acc[ma][na][0] + b0;
            float v1 = acc[ma][na][1] + b1;
            float v2 = acc[ma][na][2] + b0;
            float v3 = acc[ma][na][3] + b1;
            if (EPI == 3) {
                v0 = 0.5f * v0 * (1.0f + erff(v0 * 0.70710678118654752f));
                v1 = 0.5f * v1 * (1.0f + erff(v1 * 0.70710678118654752f));
                v2 = 0.5f * v2 * (1.0f + erff(v2 * 0.70710678118654752f));
                v3 = 0.5f * v3 * (1.0f + erff(v3 * 0.70710678118654752f));
                __nv_bfloat162 h0, l0, h1, l1;
                h0.x = __float2bfloat16(v0); h0.y = __float2bfloat16(v1);
                l0.x = __float2bfloat16(v0 - __bfloat162float(h0.x));
                l0.y = __float2bfloat16(v1 - __bfloat162float(h0.y));
                h1.x = __float2bfloat16(v2); h1.y = __float2bfloat16(v3);
                l1.x = __float2bfloat16(v2 - __bfloat162float(h1.x));
                l1.y = __float2bfloat16(v3 - __bfloat162float(h1.y));
                __nv_bfloat16* c0 = Ce + (size_t)row0 * 3 * N;
                __nv_bfloat16* c1 = Ce + (size_t)row1 * 3 * N;
                *reinterpret_cast<__nv_bfloat162*>(c0 + col)         = h0;
                *reinterpret_cast<__nv_bfloat162*>(c0 + N + col)     = l0;
                *reinterpret_cast<__nv_bfloat162*>(c0 + 2 * N + col) = h0;
                *reinterpret_cast<__nv_bfloat162*>(c1 + col)         = h1;
                *reinterpret_cast<__nv_bfloat162*>(c1 + N + col)     = l1;
                *reinterpret_cast<__nv_bfloat162*>(c1 + 2 * N + col) = h1;
            } else {
                *reinterpret_cast<float2*>(Cout + (size_t)row0 * N + col) = make_float2(v0, v1);
                *reinterpret_cast<float2*>(Cout + (size_t)row1 * N + col) = make_float2(v2, v3);
            }
        }
    }
}

// ---------------------------------------------------------------------------
// Fused masked-causal attention, 4-way key batching, 8 queries/block
// ---------------------------------------------------------------------------
__global__ __launch_bounds__(256)
void attn_kernel(const float* __restrict__ QKV, __nv_bfloat16* __restrict__ Ye)
{
    const int bh = blockIdx.x;
    const int b  = bh >> 4;
    const int h  = bh & 15;
    const int qbase = blockIdx.y * 8;
    const int warp = threadIdx.x >> 5;
    const int lane = threadIdx.x & 31;
    const int tq = qbase + warp;

    __shared__ float Ks[68][66];
    __shared__ float Vs[68][66];

    const size_t rq = (size_t)(b * T_SEQ + tq) * NQKV + h * HEAD_D;
    const float q0 = QKV[rq + lane * 2];
    const float q1 = QKV[rq + lane * 2 + 1];

    float m = -INFINITY, l = 0.f, acc0 = 0.f, acc1 = 0.f;
    const int smax = qbase + 7;

    for (int s0 = 0; s0 <= smax; s0 += 64) {
        const int tile = min(64, smax + 1 - s0);
        __syncthreads();
        for (int idx = threadIdx.x; idx < 68 * 64; idx += 256) {
            const int r = idx >> 6, cc = idx & 63;
            float kv = 0.f, vv = 0.f;
            if (r < tile) {
                const size_t g = (size_t)(b * T_SEQ + s0 + r) * NQKV + h * HEAD_D + cc;
                kv = QKV[g + C_DIM];
                vv = QKV[g + 2 * C_DIM];
            }
            Ks[r][cc] = kv; Vs[r][cc] = vv;
        }
        __syncthreads();

        const int rend = min(tq, s0 + 63) - s0;
        for (int r = 0; r <= rend; r += 4) {
            float p[4];
#pragma unroll
            for (int j = 0; j < 4; ++j)
                p[j] = q0 * Ks[r + j][lane * 2] + q1 * Ks[r + j][lane * 2 + 1];
#pragma unroll
            for (int off = 16; off; off >>= 1) {
#pragma unroll
                for (int j = 0; j < 4; ++j)
                    p[j] += __shfl_xor_sync(~0u, p[j], off);
            }
#pragma unroll
            for (int j = 0; j < 4; ++j) {
                const int s = s0 + r + j;
                const bool valid = (s <= tq) && ((s & 15) != 15);
                p[j] = valid ? p[j] * 0.125f : -INFINITY;
            }
            const float mnew = fmaxf(fmaxf(fmaxf(p[0], p[1]), fmaxf(p[2], p[3])), m);
            const float corr = __expf(m - mnew);
            const float w0 = __expf(p[0] - mnew);
            const float w1 = __expf(p[1] - mnew);
            const float w2 = __expf(p[2] - mnew);
            const float w3 = __expf(p[3] - mnew);
            l = l * corr + ((w0 + w1) + (w2 + w3));
            acc0 = acc0 * corr + w0 * Vs[r][lane * 2]     + w1 * Vs[r + 1][lane * 2]
                               + w2 * Vs[r + 2][lane * 2] + w3 * Vs[r + 3][lane * 2];
            acc1 = acc1 * corr + w0 * Vs[r][lane * 2 + 1]     + w1 * Vs[r + 1][lane * 2 + 1]
                               + w2 * Vs[r + 2][lane * 2 + 1] + w3 * Vs[r + 3][lane * 2 + 1];
            m = mnew;
        }
    }
    const float inv = 1.0f / l;
    const float o0 = acc0 * inv, o1 = acc1 * inv;

    const int row = b * T_SEQ + tq;
    const int c = h * HEAD_D + lane * 2;
    __nv_bfloat162 hi2, lo2;
    hi2.x = __float2bfloat16(o0); hi2.y = __float2bfloat16(o1);
    lo2.x = __float2bfloat16(o0 - __bfloat162float(hi2.x));
    lo2.y = __float2bfloat16(o1 - __bfloat162float(hi2.y));
    __nv_bfloat16* yr = Ye + (size_t)row * K3C;
    *reinterpret_cast<__nv_bfloat162*>(yr + c)             = hi2;
    *reinterpret_cast<__nv_bfloat162*>(yr + C_DIM + c)     = lo2;
    *reinterpret_cast<__nv_bfloat162*>(yr + 2 * C_DIM + c) = hi2;
}

// ---------------------------------------------------------------------------
// EinLinear head
// ---------------------------------------------------------------------------
__global__ __launch_bounds__(256)
void head_kernel(const float* __restrict__ X, const float* __restrict__ Wh,
                 float* __restrict__ out)
{
    const int e     = blockIdx.x & 15;
    const int chunk = blockIdx.x >> 4;
    const int tid = threadIdx.x;
    const int warp = tid >> 5, lane = tid & 31;

    __shared__ float xs[8][C_DIM];
    int rows[8];
#pragma unroll
    for (int j = 0; j < 8; ++j) rows[j] = (chunk * 8 + j) * TRANS + e;

#pragma unroll
    for (int j = 0; j < 8; ++j)
        for (int idx = tid; idx < C_DIM; idx += 256)
            xs[j][idx] = X[(size_t)rows[j] * C_DIM + idx];
    __syncthreads();

    for (int o = warp; o < VOCABP1; o += 8) {
        const float* w = Wh + ((size_t)e * VOCABP1 + o) * C_DIM;
        float a[8];
#pragma unroll
        for (int j = 0; j < 8; ++j) a[j] = 0.f;
        for (int k = lane; k < C_DIM; k += 32) {
            const float wv = w[k];
#pragma unroll
            for (int j = 0; j < 8; ++j) a[j] += wv * xs[j][k];
        }
#pragma unroll
        for (int j = 0; j < 8; ++j)
#pragma unroll
            for (int off = 16; off; off >>= 1)
                a[j] += __shfl_xor_sync(~0u, a[j], off);
        if (lane == 0) {
#pragma unroll
            for (int j = 0; j < 8; ++j)
                out[(size_t)rows[j] * VOCABP1 + o] = a[j];
        }
    }
}

// ---------------------------------------------------------------------------
// Launch. Order: expand_qkv(1), embed_ln(2), QKV GEMM(3), attn(4) <- ncu slot.
// ---------------------------------------------------------------------------
extern "C" void kernel_launch(void* const* d_in, const int* in_sizes, int n_in,
                              void* d_out, int out_size)
{
    const int*   tokens  = (const int*)  d_in[0];
    const float* tok_emb = (const float*)d_in[1];
    const float* pos_emb = (const float*)d_in[2];
    const float* Wq = (const float*)d_in[3];  const float* bq = (const float*)d_in[4];
    const float* Wk = (const float*)d_in[5];  const float* bk = (const float*)d_in[6];
    const float* Wv = (const float*)d_in[7];  const float* bv = (const float*)d_in[8];
    const float* Wp = (const float*)d_in[9];  const float* bp = (const float*)d_in[10];
    const float* ln1w = (const float*)d_in[11]; const float* ln1b = (const float*)d_in[12];
    const float* ln2w = (const float*)d_in[13]; const float* ln2b = (const float*)d_in[14];
    const float* W1 = (const float*)d_in[15]; const float* b1 = (const float*)d_in[16];
    const float* W2 = (const float*)d_in[17]; const float* b2 = (const float*)d_in[18];
    const float* lnfw = (const float*)d_in[19]; const float* lnfb = (const float*)d_in[20];
    const float* head_w = (const float*)d_in[21];

    float *x, *h, *qkv, *part;
    __nv_bfloat16 *aC, *aF, *wqkvx, *wpx, *w1x, *w2x;
    cudaGetSymbolAddress((void**)&x,    g_x);
    cudaGetSymbolAddress((void**)&h,    g_h);
    cudaGetSymbolAddress((void**)&qkv,  g_qkv);
    cudaGetSymbolAddress((void**)&part, g_part);
    cudaGetSymbolAddress((void**)&aC,   g_aexpC);
    cudaGetSymbolAddress((void**)&aF,   g_aexpF);
    cudaGetSymbolAddress((void**)&wqkvx, g_wqkv);
    cudaGetSymbolAddress((void**)&wpx,  g_wp);
    cudaGetSymbolAddress((void**)&w1x,  g_w1);
    cudaGetSymbolAddress((void**)&w2x,  g_w2);

    cudaFuncSetAttribute(mma_gemm<0>, cudaFuncAttributeMaxDynamicSharedMemorySize, G_SMEM);
    cudaFuncSetAttribute(mma_gemm<3>, cudaFuncAttributeMaxDynamicSharedMemorySize, G_SMEM);
    cudaFuncSetAttribute(mma_gemm<4>, cudaFuncAttributeMaxDynamicSharedMemorySize, G_SMEM);

    const dim3 wb(32, 8);
    const dim3 gQKV(NQKV   / 128, ROWS / 128);        // (24, 16)
    const dim3 gF4 (F4_DIM / 128, ROWS / 128);        // (32, 16)
    const dim3 gCsp(C_DIM  / 128, ROWS / 128, 2);     // (8, 16, 2) split-K
    const dim3 gAtt(B_SZ * N_HEADS, T_SEQ / 8);       // (32, 128)

    // 1: all Q/K/V weight expansions (12 z-slices)
    expand_qkv<<<dim3(32, 32, 3 * N_LAYER), wb>>>(Wq, Wk, Wv, wqkvx);
    // 2: fused embedding + layer-0 ln1
    embed_ln_kernel<<<ROWS, 256>>>(tokens, tok_emb, pos_emb, ln1w, ln1b, x, aC);
    // 3: layer-0 QKV GEMM
    mma_gemm<4><<<gQKV, 256, G_SMEM>>>(aC, wqkvx, bq, bk, bv,
                                       qkv, nullptr, NQKV, K3C, K3C);
    // 4: layer-0 attention  <-- ncu profiles our 4th launch
    attn_kernel<<<gAtt, 256>>>(qkv, aC);

    // remaining weight expansions (before first proj use)
    expand_wT<<<dim3(32, 32, N_LAYER), wb>>>(Wp, wpx,
        C_DIM, C_DIM, (size_t)C_DIM * C_DIM, (size_t)C_DIM * K3C);
    expand_wT<<<dim3(32, 128, N_LAYER), wb>>>(W1, w1x,
        C_DIM, F4_DIM, (size_t)C_DIM * F4_DIM, (size_t)F4_DIM * K3C);
    expand_wT<<<dim3(128, 32, N_LAYER), wb>>>(W2, w2x,
        F4_DIM, C_DIM, (size_t)F4_DIM * C_DIM, (size_t)C_DIM * K3F);

    for (int i = 0; i < N_LAYER; ++i) {
        const size_t bc = (size_t)i * C_DIM;

        if (i > 0) {
            mma_gemm<4><<<gQKV, 256, G_SMEM>>>(aC, wqkvx + (size_t)i * NQKV * K3C,
                                               bq + bc, bk + bc, bv + bc,
                                               qkv, nullptr, NQKV, K3C, K3C);
            attn_kernel<<<gAtt, 256>>>(qkv, aC);
        }

        // proj: split-K2 partials, then fused reduce+residual+ln2 -> aC
        mma_gemm<0><<<gCsp, 256, G_SMEM>>>(aC, wpx + (size_t)i * C_DIM * K3C,
                                           nullptr, nullptr, nullptr,
                                           part, nullptr, C_DIM, K3C, K3C / 2);
        red_ln_kernel<1><<<ROWS, 256>>>(part, bp + bc, x,
                                        ln2w + bc, ln2b + bc, nullptr, aC);

        mma_gemm<3><<<gF4, 256, G_SMEM>>>(aC, w1x + (size_t)i * F4_DIM * K3C,
                                          b1 + (size_t)i * F4_DIM, nullptr, nullptr,
                                          nullptr, aF, F4_DIM, K3C, K3C);

        // W2: split-K2 partials, then fused reduce+residual+(ln1_next | lnf)
        mma_gemm<0><<<gCsp, 256, G_SMEM>>>(aF, w2x + (size_t)i * C_DIM * K3F,
                                           nullptr, nullptr, nullptr,
                                           part, nullptr, C_DIM, K3F, K3F / 2);
        if (i < N_LAYER - 1) {
            red_ln_kernel<1><<<ROWS, 256>>>(part, b2 + bc, x,
                                            ln1w + bc + C_DIM, ln1b + bc + C_DIM,
                                            nullptr, aC);
        } else {
            red_ln_kernel<0><<<ROWS, 256>>>(part, b2 + bc, x,
                                            lnfw, lnfb, h, nullptr);
        }
    }

    head_kernel<<<256, 256>>>(h, head_w, (float*)d_out);
}

// round 16
// speedup vs baseline: 3.1565x; 1.9904x over previous
#include <cuda_runtime.h>
#include <cuda_bf16.h>
#include <cstdint>
#include <math.h>

// ---------------------------------------------------------------------------
// Model constants
// ---------------------------------------------------------------------------
#define N_LAYER 4
#define N_HEADS 16
#define C_DIM   1024
#define T_SEQ   1024
#define B_SZ    2
#define ROWS    (B_SZ * T_SEQ)      // 2048
#define F4_DIM  (4 * C_DIM)         // 4096
#define HEAD_D  64
#define VOCABP1 101
#define TRANS   16
#define K3C     (3 * C_DIM)         // 3072
#define K3F     (3 * F4_DIM)        // 12288
#define NQKV    (3 * C_DIM)         // 3072

// ---------------------------------------------------------------------------
// Static device scratch (no allocations allowed)
// ---------------------------------------------------------------------------
__device__ float g_x   [ROWS * C_DIM];
__device__ float g_h   [ROWS * C_DIM];
__device__ float g_qkv [ROWS * NQKV];
__device__ float g_part[2 * ROWS * C_DIM];            // split-K partials

__device__ __nv_bfloat16 g_aexpC[(size_t)ROWS * K3C];
__device__ __nv_bfloat16 g_aexpF[(size_t)ROWS * K3F];

__device__ __nv_bfloat16 g_wqkv[(size_t)N_LAYER * NQKV * K3C];
__device__ __nv_bfloat16 g_wp  [(size_t)N_LAYER * C_DIM * K3C];
__device__ __nv_bfloat16 g_w1  [(size_t)N_LAYER * F4_DIM * K3C];
__device__ __nv_bfloat16 g_w2  [(size_t)N_LAYER * C_DIM * K3F];

// ---------------------------------------------------------------------------
// PTX helpers (sm_80-safe only; ptxas targets plain sm_103)
// ---------------------------------------------------------------------------
__device__ __forceinline__ uint32_t smem_u32(const void* p) {
    uint32_t a;
    asm("{ .reg .u64 t; cvta.to.shared.u64 t, %1; cvt.u32.u64 %0, t; }" : "=r"(a) : "l"(p));
    return a;
}
__device__ __forceinline__ void cp_async16(uint32_t s, const void* g) {
    asm volatile("cp.async.cg.shared.global [%0], [%1], 16;" :: "r"(s), "l"(g));
}
__device__ __forceinline__ void cp_commit() { asm volatile("cp.async.commit_group;"); }
template<int N> __device__ __forceinline__ void cp_wait() {
    asm volatile("cp.async.wait_group %0;" :: "n"(N));
}
__device__ __forceinline__ void ldsm_x4(uint32_t& r0, uint32_t& r1, uint32_t& r2, uint32_t& r3,
                                        uint32_t addr) {
    asm volatile("ldmatrix.sync.aligned.m8n8.x4.shared.b16 {%0,%1,%2,%3}, [%4];"
                 : "=r"(r0), "=r"(r1), "=r"(r2), "=r"(r3) : "r"(addr));
}
__device__ __forceinline__ void mma16816(float* c, const uint32_t* a, uint32_t b0, uint32_t b1) {
    asm volatile("mma.sync.aligned.m16n8k16.row.col.f32.bf16.bf16.f32 "
                 "{%0,%1,%2,%3}, {%4,%5,%6,%7}, {%8,%9}, {%0,%1,%2,%3};"
                 : "+f"(c[0]), "+f"(c[1]), "+f"(c[2]), "+f"(c[3])
                 : "r"(a[0]), "r"(a[1]), "r"(a[2]), "r"(a[3]), "r"(b0), "r"(b1));
}
__device__ __forceinline__ uint32_t swz(int r, int s8) {
    return (uint32_t)(r * 128 + ((s8 ^ (r & 7)) << 4));
}

// ---------------------------------------------------------------------------
// LayerNorm core. EXP=0: fp32 Y. EXP=1: bf16 [hi|lo|hi] into Ye [row][3C]
// ---------------------------------------------------------------------------
template<int EXP>
__device__ __forceinline__ void ln_core(const float v[4], int row, int tid,
                                        const float* __restrict__ w,
                                        const float* __restrict__ b,
                                        float* __restrict__ Y,
                                        __nv_bfloat16* __restrict__ Ye)
{
    __shared__ float red[8];
    float s = v[0] + v[1] + v[2] + v[3];
#pragma unroll
    for (int off = 16; off; off >>= 1) s += __shfl_xor_sync(~0u, s, off);
    if ((tid & 31) == 0) red[tid >> 5] = s;
    __syncthreads();
    float tot = 0.f;
#pragma unroll
    for (int j = 0; j < 8; ++j) tot += red[j];
    const float mu = tot * (1.0f / C_DIM);
    __syncthreads();

    float ss = 0.f;
#pragma unroll
    for (int i = 0; i < 4; ++i) { float d = v[i] - mu; ss += d * d; }
#pragma unroll
    for (int off = 16; off; off >>= 1) ss += __shfl_xor_sync(~0u, ss, off);
    if ((tid & 31) == 0) red[tid >> 5] = ss;
    __syncthreads();
    float tot2 = 0.f;
#pragma unroll
    for (int j = 0; j < 8; ++j) tot2 += red[j];
    const float rs = rsqrtf(tot2 * (1.0f / C_DIM) + 1e-5f);

#pragma unroll
    for (int i = 0; i < 4; ++i) {
        const int c = tid + 256 * i;
        const float o = (v[i] - mu) * rs * w[c] + b[c];
        if (EXP == 0) {
            Y[(size_t)row * C_DIM + c] = o;
        } else {
            __nv_bfloat16 hi = __float2bfloat16(o);
            __nv_bfloat16 lo = __float2bfloat16(o - __bfloat162float(hi));
            __nv_bfloat16* yr = Ye + (size_t)row * K3C;
            yr[c]             = hi;
            yr[C_DIM + c]     = lo;
            yr[2 * C_DIM + c] = hi;
        }
    }
}

// ---------------------------------------------------------------------------
// Fused embedding + layer-0 ln1
// ---------------------------------------------------------------------------
__global__ void embed_ln_kernel(const int* __restrict__ tokens,
                                const float* __restrict__ tok_emb,
                                const float* __restrict__ pos_emb,
                                const float* __restrict__ w,
                                const float* __restrict__ b,
                                float* __restrict__ X,
                                __nv_bfloat16* __restrict__ Ye)
{
    const int row = blockIdx.x;
    const int tid = threadIdx.x;
    const int t   = row & 1023;
    const int tok = tokens[row];
    float v[4];
#pragma unroll
    for (int i = 0; i < 4; ++i) {
        const int c = tid + 256 * i;
        const float o = tok_emb[(size_t)tok * C_DIM + c] + pos_emb[(size_t)t * C_DIM + c];
        X[(size_t)row * C_DIM + c] = o;
        v[i] = o;
    }
    ln_core<1>(v, row, tid, w, b, nullptr, Ye);
}

// ---------------------------------------------------------------------------
// Fused split-K reduce + residual update + LayerNorm
// ---------------------------------------------------------------------------
template<int EXP>
__global__ void red_ln_kernel(const float* __restrict__ P,
                              const float* __restrict__ bias,
                              float* __restrict__ X,
                              const float* __restrict__ w,
                              const float* __restrict__ b,
                              float* __restrict__ Y, __nv_bfloat16* __restrict__ Ye)
{
    const int row = blockIdx.x;
    const int tid = threadIdx.x;
    const size_t base = (size_t)row * C_DIM;
    float v[4];
#pragma unroll
    for (int i = 0; i < 4; ++i) {
        const int c = tid + 256 * i;
        const float t = X[base + c] + P[base + c] + P[ROWS * C_DIM + base + c] + bias[c];
        X[base + c] = t;
        v[i] = t;
    }
    ln_core<EXP>(v, row, tid, w, b, Y, Ye);
}

// ---------------------------------------------------------------------------
// Weight expansion kernels
// ---------------------------------------------------------------------------
__global__ void expand_wT(const float* __restrict__ W, __nv_bfloat16* __restrict__ out,
                          int K, int N, size_t wstride, size_t ostride)
{
    W   += (size_t)blockIdx.z * wstride;
    out += (size_t)blockIdx.z * ostride;
    __shared__ float t[32][33];
    const int k0 = blockIdx.x * 32, n0 = blockIdx.y * 32;
    const int tx = threadIdx.x, ty = threadIdx.y;
#pragma unroll
    for (int i = 0; i < 4; ++i)
        t[ty + 8 * i][tx] = W[(size_t)(k0 + ty + 8 * i) * N + n0 + tx];
    __syncthreads();
#pragma unroll
    for (int i = 0; i < 4; ++i) {
        int n = n0 + ty + 8 * i;
        int k = k0 + tx;
        float x = t[tx][ty + 8 * i];
        __nv_bfloat16 hi = __float2bfloat16(x);
        __nv_bfloat16 lo = __float2bfloat16(x - __bfloat162float(hi));
        size_t base = (size_t)n * 3 * K;
        out[base + k]         = hi;
        out[base + K + k]     = hi;
        out[base + 2 * K + k] = lo;
    }
}

__global__ void expand_qkv(const float* __restrict__ Wq, const float* __restrict__ Wk,
                           const float* __restrict__ Wv, __nv_bfloat16* __restrict__ out)
{
    const int mat   = blockIdx.z % 3;
    const int layer = blockIdx.z / 3;
    const float* W = (mat == 0) ? Wq : (mat == 1) ? Wk : Wv;
    W   += (size_t)layer * C_DIM * C_DIM;
    out += (size_t)layer * NQKV * K3C + (size_t)mat * C_DIM * K3C;

    __shared__ float t[32][33];
    const int k0 = blockIdx.x * 32, n0 = blockIdx.y * 32;
    const int tx = threadIdx.x, ty = threadIdx.y;
#pragma unroll
    for (int i = 0; i < 4; ++i)
        t[ty + 8 * i][tx] = W[(size_t)(k0 + ty + 8 * i) * C_DIM + n0 + tx];
    __syncthreads();
#pragma unroll
    for (int i = 0; i < 4; ++i) {
        int n = n0 + ty + 8 * i;
        int k = k0 + tx;
        float x = t[tx][ty + 8 * i];
        __nv_bfloat16 hi = __float2bfloat16(x);
        __nv_bfloat16 lo = __float2bfloat16(x - __bfloat162float(hi));
        size_t base = (size_t)n * K3C;
        out[base + k]             = hi;
        out[base + C_DIM + k]     = hi;
        out[base + 2 * C_DIM + k] = lo;
    }
}

// ---------------------------------------------------------------------------
// HMMA bf16 GEMM (unchanged, validated)
// ---------------------------------------------------------------------------
#define G_STAGES 3
#define G_TILEB  (128 * 128)
#define G_STAGEB (2 * G_TILEB)
#define G_SMEM   (G_STAGES * G_STAGEB)   // 98304

template<int EPI>
__global__ __launch_bounds__(256, 2)
void mma_gemm(const __nv_bfloat16* __restrict__ A, const __nv_bfloat16* __restrict__ B,
              const float* __restrict__ bias, const float* __restrict__ biasK,
              const float* __restrict__ biasV,
              float* __restrict__ Cf, __nv_bfloat16* __restrict__ Ce,
              int N, int Kfull, int Ksub)
{
    extern __shared__ char smem[];
    const uint32_t sbase = smem_u32(smem);
    const int tid  = threadIdx.x;
    const int wid  = tid >> 5, lane = tid & 31;
    const int warp_m = wid >> 2, warp_n = wid & 3;
    const int bx = blockIdx.x, by = blockIdx.y, bz = blockIdx.z;

    const char* Abase = (const char*)(A + (size_t)(by * 128) * Kfull + (size_t)bz * Ksub);
    const char* Bbase = (const char*)(B + (size_t)(bx * 128) * Kfull + (size_t)bz * Ksub);
    const size_t ldg = (size_t)Kfull * 2;
    const int nchunks = Ksub >> 6;

    const int r_cp[4] = { tid >> 3, (tid + 256) >> 3, (tid + 512) >> 3, (tid + 768) >> 3 };
    const int s8_cp   = tid & 7;

#pragma unroll
    for (int st = 0; st < G_STAGES - 1; ++st) {
        const uint32_t sb = sbase + st * G_STAGEB;
#pragma unroll
        for (int p = 0; p < 4; ++p) {
            const int r = r_cp[p];
            cp_async16(sb + swz(r, s8_cp),           Abase + (size_t)r * ldg + st * 128 + s8_cp * 16);
            cp_async16(sb + G_TILEB + swz(r, s8_cp), Bbase + (size_t)r * ldg + st * 128 + s8_cp * 16);
        }
        cp_commit();
    }

    float acc[4][4][4];
#pragma unroll
    for (int i = 0; i < 4; ++i)
#pragma unroll
        for (int j = 0; j < 4; ++j)
#pragma unroll
            for (int r = 0; r < 4; ++r) acc[i][j][r] = 0.f;

    const int a_r0 = warp_m * 64 + (lane & 15);
    const int a_s0 = lane >> 4;
    const int b_r0 = warp_n * 32 + (lane & 7) + ((lane >> 4) << 3);
    const int b_s0 = (lane >> 3) & 1;

    for (int c = 0; c < nchunks; ++c) {
        cp_wait<G_STAGES - 2>();
        __syncthreads();

        const int nc = c + G_STAGES - 1;
        if (nc < nchunks) {
            const uint32_t nb = sbase + (nc % G_STAGES) * G_STAGEB;
#pragma unroll
            for (int p = 0; p < 4; ++p) {
                const int r = r_cp[p];
                cp_async16(nb + swz(r, s8_cp),           Abase + (size_t)r * ldg + nc * 128 + s8_cp * 16);
                cp_async16(nb + G_TILEB + swz(r, s8_cp), Bbase + (size_t)r * ldg + nc * 128 + s8_cp * 16);
            }
        }
        cp_commit();

        const uint32_t sb = sbase + (c % G_STAGES) * G_STAGEB;
#pragma unroll
        for (int ks = 0; ks < 4; ++ks) {
            uint32_t af[4][4], bfr[2][4];
#pragma unroll
            for (int ma = 0; ma < 4; ++ma) {
                const int r = a_r0 + ma * 16;
                ldsm_x4(af[ma][0], af[ma][1], af[ma][2], af[ma][3],
                        sb + swz(r, ks * 2 + a_s0));
            }
#pragma unroll
            for (int j = 0; j < 2; ++j) {
                const int r = b_r0 + j * 16;
                ldsm_x4(bfr[j][0], bfr[j][1], bfr[j][2], bfr[j][3],
                        sb + G_TILEB + swz(r, ks * 2 + b_s0));
            }
#pragma unroll
            for (int ma = 0; ma < 4; ++ma)
#pragma unroll
                for (int na = 0; na < 4; ++na)
                    mma16816(acc[ma][na], af[ma], bfr[na >> 1][(na & 1) * 2],
                             bfr[na >> 1][(na & 1) * 2 + 1]);
        }
    }

    float* Cout = (EPI == 0) ? (Cf + (size_t)bz * ROWS * N) : Cf;
#pragma unroll
    for (int ma = 0; ma < 4; ++ma) {
        const int row0 = by * 128 + warp_m * 64 + ma * 16 + (lane >> 2);
        const int row1 = row0 + 8;
#pragma unroll
        for (int na = 0; na < 4; ++na) {
            const int col = bx * 128 + warp_n * 32 + na * 8 + (lane & 3) * 2;
            if (EPI == 0) {
                *reinterpret_cast<float2*>(Cout + (size_t)row0 * N + col) =
                    make_float2(acc[ma][na][0], acc[ma][na][1]);
                *reinterpret_cast<float2*>(Cout + (size_t)row1 * N + col) =
                    make_float2(acc[ma][na][2], acc[ma][na][3]);
                continue;
            }
            float b0, b1;
            if (EPI == 4) {
                b0 = (col < C_DIM) ? bias[col]
                   : (col < 2 * C_DIM) ? biasK[col - C_DIM] : biasV[col - 2 * C_DIM];
                b1 = (col + 1 < C_DIM) ? bias[col + 1]
                   : (col + 1 < 2 * C_DIM) ? biasK[col + 1 - C_DIM] : biasV[col + 1 - 2 * C_DIM];
            } else {
                b0 = bias[col]; b1 = bias[col + 1];
            }
            float v0 = acc[ma][na][0] + b0;
            float v1 = acc[ma][na][1] + b1;
            float v2 = acc[ma][na][2] + b0;
            float v3 = acc[ma][na][3] + b1;
            if (EPI == 3) {
                v0 = 0.5f * v0 * (1.0f + erff(v0 * 0.70710678118654752f));
                v1 = 0.5f * v1 * (1.0f + erff(v1 * 0.70710678118654752f));
                v2 = 0.5f * v2 * (1.0f + erff(v2 * 0.70710678118654752f));
                v3 = 0.5f * v3 * (1.0f + erff(v3 * 0.70710678118654752f));
                __nv_bfloat162 h0, l0, h1, l1;
                h0.x = __float2bfloat16(v0); h0.y = __float2bfloat16(v1);
                l0.x = __float2bfloat16(v0 - __bfloat162float(h0.x));
                l0.y = __float2bfloat16(v1 - __bfloat162float(h0.y));
                h1.x = __float2bfloat16(v2); h1.y = __float2bfloat16(v3);
                l1.x = __float2bfloat16(v2 - __bfloat162float(h1.x));
                l1.y = __float2bfloat16(v3 - __bfloat162float(h1.y));
                __nv_bfloat16* c0 = Ce + (size_t)row0 * 3 * N;
                __nv_bfloat16* c1 = Ce + (size_t)row1 * 3 * N;
                *reinterpret_cast<__nv_bfloat162*>(c0 + col)         = h0;
                *reinterpret_cast<__nv_bfloat162*>(c0 + N + col)     = l0;
                *reinterpret_cast<__nv_bfloat162*>(c0 + 2 * N + col) = h0;
                *reinterpret_cast<__nv_bfloat162*>(c1 + col)         = h1;
                *reinterpret_cast<__nv_bfloat162*>(c1 + N + col)     = l1;
                *reinterpret_cast<__nv_bfloat162*>(c1 + 2 * N + col) = h1;
            } else {
                *reinterpret_cast<float2*>(Cout + (size_t)row0 * N + col) = make_float2(v0, v1);
                *reinterpret_cast<float2*>(Cout + (size_t)row1 * N + col) = make_float2(v2, v3);
            }
        }
    }
}

// ---------------------------------------------------------------------------
// MMA flash attention. Block = 256 thr (8 warps = 2m x 4n), 64-query tile.
// S = Q*K^T and O += P*V on HMMA with 3-term bf16 split; online softmax.
// SMEM layout (bytes): Qh 0, Ql 8K, Kh 16K, Kl 24K, Vth 32K, Vtl 40K,
//                      Ph 48K, Pl 56K, m/l/corr/wred @64K. Total 68352.
// ---------------------------------------------------------------------------
#define ATT_SMEM 69632

__global__ __launch_bounds__(256, 2)
void attn_mma(const float* __restrict__ QKV, __nv_bfloat16* __restrict__ Ye)
{
    extern __shared__ char sm[];
    const uint32_t sb = smem_u32(sm);
    const uint32_t QHo = 0, QLo = 8192, KHo = 16384, KLo = 24576,
                   VHo = 32768, VLo = 40960, PHo = 49152, PLo = 57344;
    float* m_row = (float*)(sm + 65536);
    float* l_row = (float*)(sm + 65792);
    float* crw   = (float*)(sm + 66048);
    float* wred  = (float*)(sm + 66304);   // [4][64]

    const int bh = blockIdx.x, b = bh >> 4, h = bh & 15;
    const int qt = (int)gridDim.y - 1 - (int)blockIdx.y;   // heavy tiles first
    const int q0 = qt * 64;
    const int tid = threadIdx.x, lane = tid & 31, wid = tid >> 5;
    const int warp_m = wid >> 2, warp_n = wid & 3;
    const int r_q = lane >> 2, cq = lane & 3;

    // load Q tile (scale folded), split hi/lo, swizzled row-major [query][dim]
    for (int idx = tid; idx < 64 * 64; idx += 256) {
        const int r = idx >> 6, d = idx & 63;
        const float q = QKV[(size_t)(b * T_SEQ + q0 + r) * NQKV + h * HEAD_D + d] * 0.125f;
        const __nv_bfloat16 hi = __float2bfloat16(q);
        const __nv_bfloat16 lo = __float2bfloat16(q - __bfloat162float(hi));
        const uint32_t off = swz(r, d >> 3) + (d & 7) * 2;
        *(__nv_bfloat16*)(sm + QHo + off) = hi;
        *(__nv_bfloat16*)(sm + QLo + off) = lo;
    }
    if (tid < 64) { m_row[tid] = -INFINITY; l_row[tid] = 0.f; }

    float of[2][2][4];
#pragma unroll
    for (int i = 0; i < 2; ++i)
#pragma unroll
        for (int j = 0; j < 2; ++j)
#pragma unroll
            for (int e = 0; e < 4; ++e) of[i][j][e] = 0.f;

    for (int kt = 0; kt <= qt; ++kt) {
        const int k0 = kt * 64;
        __syncthreads();
        // load K (row-major keys x dims) and V (TRANSPOSED dims x keys), hi/lo
        for (int idx = tid; idx < 64 * 64; idx += 256) {
            const int r = idx >> 6, d = idx & 63;
            const size_t g = (size_t)(b * T_SEQ + k0 + r) * NQKV + h * HEAD_D + d;
            const float kv = QKV[g + C_DIM];
            const float vv = QKV[g + 2 * C_DIM];
            const __nv_bfloat16 khi = __float2bfloat16(kv);
            const __nv_bfloat16 klo = __float2bfloat16(kv - __bfloat162float(khi));
            const uint32_t koff = swz(r, d >> 3) + (d & 7) * 2;
            *(__nv_bfloat16*)(sm + KHo + koff) = khi;
            *(__nv_bfloat16*)(sm + KLo + koff) = klo;
            const __nv_bfloat16 vhi = __float2bfloat16(vv);
            const __nv_bfloat16 vlo = __float2bfloat16(vv - __bfloat162float(vhi));
            const uint32_t voff = swz(d, r >> 3) + (r & 7) * 2;
            *(__nv_bfloat16*)(sm + VHo + voff) = vhi;
            *(__nv_bfloat16*)(sm + VLo + voff) = vlo;
        }
        __syncthreads();

        // ---- S = Q K^T (3-term split) ----
        float sf[2][2][4];
#pragma unroll
        for (int i = 0; i < 2; ++i)
#pragma unroll
            for (int j = 0; j < 2; ++j)
#pragma unroll
                for (int e = 0; e < 4; ++e) sf[i][j][e] = 0.f;
#pragma unroll
        for (int p = 0; p < 3; ++p) {
            const uint32_t Ab = sb + ((p == 1) ? QLo : QHo);
            const uint32_t Bb = sb + ((p == 2) ? KLo : KHo);
#pragma unroll
            for (int ks = 0; ks < 4; ++ks) {
                uint32_t af[2][4], bf4[4];
#pragma unroll
                for (int ma = 0; ma < 2; ++ma)
                    ldsm_x4(af[ma][0], af[ma][1], af[ma][2], af[ma][3],
                            Ab + swz(warp_m * 32 + ma * 16 + (lane & 15), ks * 2 + (lane >> 4)));
                ldsm_x4(bf4[0], bf4[1], bf4[2], bf4[3],
                        Bb + swz(warp_n * 16 + (lane & 7) + ((lane >> 4) << 3),
                                 ks * 2 + ((lane >> 3) & 1)));
#pragma unroll
                for (int ma = 0; ma < 2; ++ma)
#pragma unroll
                    for (int na = 0; na < 2; ++na)
                        mma16816(sf[ma][na], af[ma], bf4[na * 2], bf4[na * 2 + 1]);
            }
        }

        // ---- mask + row max ----
        float rmax[2][2] = { {-INFINITY, -INFINITY}, {-INFINITY, -INFINITY} };
#pragma unroll
        for (int ma = 0; ma < 2; ++ma)
#pragma unroll
            for (int na = 0; na < 2; ++na)
#pragma unroll
                for (int e = 0; e < 4; ++e) {
                    const int row_l = warp_m * 32 + ma * 16 + r_q + (e >> 1) * 8;
                    const int key   = k0 + warp_n * 16 + na * 8 + cq * 2 + (e & 1);
                    const bool valid = (key <= q0 + row_l) && ((key & 15) != 15);
                    const float v = valid ? sf[ma][na][e] : -INFINITY;
                    sf[ma][na][e] = v;
                    rmax[ma][e >> 1] = fmaxf(rmax[ma][e >> 1], v);
                }
#pragma unroll
        for (int ma = 0; ma < 2; ++ma)
#pragma unroll
            for (int hf = 0; hf < 2; ++hf) {
                float v = rmax[ma][hf];
                v = fmaxf(v, __shfl_xor_sync(~0u, v, 1));
                v = fmaxf(v, __shfl_xor_sync(~0u, v, 2));
                rmax[ma][hf] = v;
            }
        if (cq == 0) {
#pragma unroll
            for (int ma = 0; ma < 2; ++ma)
#pragma unroll
                for (int hf = 0; hf < 2; ++hf)
                    wred[warp_n * 64 + warp_m * 32 + ma * 16 + r_q + hf * 8] = rmax[ma][hf];
        }
        __syncthreads();
        if (tid < 64) {
            const float mo = m_row[tid];
            float mn = fmaxf(fmaxf(wred[tid], wred[64 + tid]),
                             fmaxf(wred[128 + tid], wred[192 + tid]));
            mn = fmaxf(mn, mo);
            const float c = __expf(mo - mn);
            crw[tid] = c;
            m_row[tid] = mn;
            l_row[tid] *= c;
        }
        __syncthreads();

        // ---- P = exp(S - m); write Ph/Pl; scale O; row sums ----
        float m4[2][2], c4[2][2];
#pragma unroll
        for (int ma = 0; ma < 2; ++ma)
#pragma unroll
            for (int hf = 0; hf < 2; ++hf) {
                const int row_l = warp_m * 32 + ma * 16 + r_q + hf * 8;
                m4[ma][hf] = m_row[row_l];
                c4[ma][hf] = crw[row_l];
            }
        float rs[2][2] = { {0.f, 0.f}, {0.f, 0.f} };
#pragma unroll
        for (int ma = 0; ma < 2; ++ma)
#pragma unroll
            for (int na = 0; na < 2; ++na) {
                const float p0 = __expf(sf[ma][na][0] - m4[ma][0]);
                const float p1 = __expf(sf[ma][na][1] - m4[ma][0]);
                const float p2 = __expf(sf[ma][na][2] - m4[ma][1]);
                const float p3 = __expf(sf[ma][na][3] - m4[ma][1]);
                rs[ma][0] += p0 + p1;
                rs[ma][1] += p2 + p3;
                const int colb = warp_n * 16 + na * 8 + cq * 2;
                const int row0 = warp_m * 32 + ma * 16 + r_q;
                const uint32_t o0 = swz(row0, colb >> 3) + (colb & 7) * 2;
                const uint32_t o1 = swz(row0 + 8, colb >> 3) + (colb & 7) * 2;
                __nv_bfloat162 h2, l2;
                h2.x = __float2bfloat16(p0); h2.y = __float2bfloat16(p1);
                l2.x = __float2bfloat16(p0 - __bfloat162float(h2.x));
                l2.y = __float2bfloat16(p1 - __bfloat162float(h2.y));
                *(__nv_bfloat162*)(sm + PHo + o0) = h2;
                *(__nv_bfloat162*)(sm + PLo + o0) = l2;
                h2.x = __float2bfloat16(p2); h2.y = __float2bfloat16(p3);
                l2.x = __float2bfloat16(p2 - __bfloat162float(h2.x));
                l2.y = __float2bfloat16(p3 - __bfloat162float(h2.y));
                *(__nv_bfloat162*)(sm + PHo + o1) = h2;
                *(__nv_bfloat162*)(sm + PLo + o1) = l2;
                of[ma][na][0] *= c4[ma][0];
                of[ma][na][1] *= c4[ma][0];
                of[ma][na][2] *= c4[ma][1];
                of[ma][na][3] *= c4[ma][1];
            }
#pragma unroll
        for (int ma = 0; ma < 2; ++ma)
#pragma unroll
            for (int hf = 0; hf < 2; ++hf) {
                float v = rs[ma][hf];
                v += __shfl_xor_sync(~0u, v, 1);
                v += __shfl_xor_sync(~0u, v, 2);
                rs[ma][hf] = v;
            }
        if (cq == 0) {
#pragma unroll
            for (int ma = 0; ma < 2; ++ma)
#pragma unroll
                for (int hf = 0; hf < 2; ++hf)
                    wred[warp_n * 64 + warp_m * 32 + ma * 16 + r_q + hf * 8] = rs[ma][hf];
        }
        __syncthreads();
        if (tid < 64)
            l_row[tid] += wred[tid] + wred[64 + tid] + wred[128 + tid] + wred[192 + tid];

        // ---- O += P V (3-term split); B = V^T (dims x keys) ----
#pragma unroll
        for (int p = 0; p < 3; ++p) {
            const uint32_t Ab = sb + ((p == 1) ? PLo : PHo);
            const uint32_t Bb = sb + ((p == 2) ? VLo : VHo);
#pragma unroll
            for (int ks = 0; ks < 4; ++ks) {
                uint32_t af[2][4], bf4[4];
#pragma unroll
                for (int ma = 0; ma < 2; ++ma)
                    ldsm_x4(af[ma][0], af[ma][1], af[ma][2], af[ma][3],
                            Ab + swz(warp_m * 32 + ma * 16 + (lane & 15), ks * 2 + (lane >> 4)));
                ldsm_x4(bf4[0], bf4[1], bf4[2], bf4[3],
                        Bb + swz(warp_n * 16 + (lane & 7) + ((lane >> 4) << 3),
                                 ks * 2 + ((lane >> 3) & 1)));
#pragma unroll
                for (int ma = 0; ma < 2; ++ma)
#pragma unroll
                    for (int na = 0; na < 2; ++na)
                        mma16816(of[ma][na], af[ma], bf4[na * 2], bf4[na * 2 + 1]);
            }
        }
    }

    // ---- finalize: O /= l; write expanded bf16 [hi|lo|hi] ----
    __syncthreads();
    if (tid < 64) crw[tid] = 1.0f / l_row[tid];
    __syncthreads();
    float i4[2][2];
#pragma unroll
    for (int ma = 0; ma < 2; ++ma)
#pragma unroll
        for (int hf = 0; hf < 2; ++hf)
            i4[ma][hf] = crw[warp_m * 32 + ma * 16 + r_q + hf * 8];
#pragma unroll
    for (int ma = 0; ma < 2; ++ma)
#pragma unroll
        for (int na = 0; na < 2; ++na) {
            const int row0 = warp_m * 32 + ma * 16 + r_q;
            const int col  = h * HEAD_D + warp_n * 16 + na * 8 + cq * 2;
#pragma unroll
            for (int hf = 0; hf < 2; ++hf) {
                const float v0 = of[ma][na][hf * 2]     * i4[ma][hf];
                const float v1 = of[ma][na][hf * 2 + 1] * i4[ma][hf];
                __nv_bfloat162 hi2, lo2;
                hi2.x = __float2bfloat16(v0); hi2.y = __float2bfloat16(v1);
                lo2.x = __float2bfloat16(v0 - __bfloat162float(hi2.x));
                lo2.y = __float2bfloat16(v1 - __bfloat162float(hi2.y));
                __nv_bfloat16* yr = Ye + (size_t)(b * T_SEQ + q0 + row0 + hf * 8) * K3C;
                *reinterpret_cast<__nv_bfloat162*>(yr + col)             = hi2;
                *reinterpret_cast<__nv_bfloat162*>(yr + C_DIM + col)     = lo2;
                *reinterpret_cast<__nv_bfloat162*>(yr + 2 * C_DIM + col) = hi2;
            }
        }
}

// ---------------------------------------------------------------------------
// EinLinear head
// ---------------------------------------------------------------------------
__global__ __launch_bounds__(256)
void head_kernel(const float* __restrict__ X, const float* __restrict__ Wh,
                 float* __restrict__ out)
{
    const int e     = blockIdx.x & 15;
    const int chunk = blockIdx.x >> 4;
    const int tid = threadIdx.x;
    const int warp = tid >> 5, lane = tid & 31;

    __shared__ float xs[8][C_DIM];
    int rows[8];
#pragma unroll
    for (int j = 0; j < 8; ++j) rows[j] = (chunk * 8 + j) * TRANS + e;

#pragma unroll
    for (int j = 0; j < 8; ++j)
        for (int idx = tid; idx < C_DIM; idx += 256)
            xs[j][idx] = X[(size_t)rows[j] * C_DIM + idx];
    __syncthreads();

    for (int o = warp; o < VOCABP1; o += 8) {
        const float* w = Wh + ((size_t)e * VOCABP1 + o) * C_DIM;
        float a[8];
#pragma unroll
        for (int j = 0; j < 8; ++j) a[j] = 0.f;
        for (int k = lane; k < C_DIM; k += 32) {
            const float wv = w[k];
#pragma unroll
            for (int j = 0; j < 8; ++j) a[j] += wv * xs[j][k];
        }
#pragma unroll
        for (int j = 0; j < 8; ++j)
#pragma unroll
            for (int off = 16; off; off >>= 1)
                a[j] += __shfl_xor_sync(~0u, a[j], off);
        if (lane == 0) {
#pragma unroll
            for (int j = 0; j < 8; ++j)
                out[(size_t)rows[j] * VOCABP1 + o] = a[j];
        }
    }
}

// ---------------------------------------------------------------------------
// Launch. Order: expand_qkv(1), embed_ln(2), QKV GEMM(3), attn_mma(4) <- ncu.
// ---------------------------------------------------------------------------
extern "C" void kernel_launch(void* const* d_in, const int* in_sizes, int n_in,
                              void* d_out, int out_size)
{
    const int*   tokens  = (const int*)  d_in[0];
    const float* tok_emb = (const float*)d_in[1];
    const float* pos_emb = (const float*)d_in[2];
    const float* Wq = (const float*)d_in[3];  const float* bq = (const float*)d_in[4];
    const float* Wk = (const float*)d_in[5];  const float* bk = (const float*)d_in[6];
    const float* Wv = (const float*)d_in[7];  const float* bv = (const float*)d_in[8];
    const float* Wp = (const float*)d_in[9];  const float* bp = (const float*)d_in[10];
    const float* ln1w = (const float*)d_in[11]; const float* ln1b = (const float*)d_in[12];
    const float* ln2w = (const float*)d_in[13]; const float* ln2b = (const float*)d_in[14];
    const float* W1 = (const float*)d_in[15]; const float* b1 = (const float*)d_in[16];
    const float* W2 = (const float*)d_in[17]; const float* b2 = (const float*)d_in[18];
    const float* lnfw = (const float*)d_in[19]; const float* lnfb = (const float*)d_in[20];
    const float* head_w = (const float*)d_in[21];

    float *x, *h, *qkv, *part;
    __nv_bfloat16 *aC, *aF, *wqkvx, *wpx, *w1x, *w2x;
    cudaGetSymbolAddress((void**)&x,    g_x);
    cudaGetSymbolAddress((void**)&h,    g_h);
    cudaGetSymbolAddress((void**)&qkv,  g_qkv);
    cudaGetSymbolAddress((void**)&part, g_part);
    cudaGetSymbolAddress((void**)&aC,   g_aexpC);
    cudaGetSymbolAddress((void**)&aF,   g_aexpF);
    cudaGetSymbolAddress((void**)&wqkvx, g_wqkv);
    cudaGetSymbolAddress((void**)&wpx,  g_wp);
    cudaGetSymbolAddress((void**)&w1x,  g_w1);
    cudaGetSymbolAddress((void**)&w2x,  g_w2);

    cudaFuncSetAttribute(mma_gemm<0>, cudaFuncAttributeMaxDynamicSharedMemorySize, G_SMEM);
    cudaFuncSetAttribute(mma_gemm<3>, cudaFuncAttributeMaxDynamicSharedMemorySize, G_SMEM);
    cudaFuncSetAttribute(mma_gemm<4>, cudaFuncAttributeMaxDynamicSharedMemorySize, G_SMEM);
    cudaFuncSetAttribute(attn_mma,   cudaFuncAttributeMaxDynamicSharedMemorySize, ATT_SMEM);

    const dim3 wb(32, 8);
    const dim3 gQKV(NQKV   / 128, ROWS / 128);        // (24, 16)
    const dim3 gF4 (F4_DIM / 128, ROWS / 128);        // (32, 16)
    const dim3 gCsp(C_DIM  / 128, ROWS / 128, 2);     // (8, 16, 2) split-K
    const dim3 gAtt(B_SZ * N_HEADS, T_SEQ / 64);      // (32, 16)

    // 1: all Q/K/V weight expansions
    expand_qkv<<<dim3(32, 32, 3 * N_LAYER), wb>>>(Wq, Wk, Wv, wqkvx);
    // 2: fused embedding + layer-0 ln1
    embed_ln_kernel<<<ROWS, 256>>>(tokens, tok_emb, pos_emb, ln1w, ln1b, x, aC);
    // 3: layer-0 QKV GEMM
    mma_gemm<4><<<gQKV, 256, G_SMEM>>>(aC, wqkvx, bq, bk, bv,
                                       qkv, nullptr, NQKV, K3C, K3C);
    // 4: layer-0 attention (MMA)  <-- ncu profiles our 4th launch
    attn_mma<<<gAtt, 256, ATT_SMEM>>>(qkv, aC);

    // remaining weight expansions
    expand_wT<<<dim3(32, 32, N_LAYER), wb>>>(Wp, wpx,
        C_DIM, C_DIM, (size_t)C_DIM * C_DIM, (size_t)C_DIM * K3C);
    expand_wT<<<dim3(32, 128, N_LAYER), wb>>>(W1, w1x,
        C_DIM, F4_DIM, (size_t)C_DIM * F4_DIM, (size_t)F4_DIM * K3C);
    expand_wT<<<dim3(128, 32, N_LAYER), wb>>>(W2, w2x,
        F4_DIM, C_DIM, (size_t)F4_DIM * C_DIM, (size_t)C_DIM * K3F);

    for (int i = 0; i < N_LAYER; ++i) {
        const size_t bc = (size_t)i * C_DIM;

        if (i > 0) {
            mma_gemm<4><<<gQKV, 256, G_SMEM>>>(aC, wqkvx + (size_t)i * NQKV * K3C,
                                               bq + bc, bk + bc, bv + bc,
                                               qkv, nullptr, NQKV, K3C, K3C);
            attn_mma<<<gAtt, 256, ATT_SMEM>>>(qkv, aC);
        }

        mma_gemm<0><<<gCsp, 256, G_SMEM>>>(aC, wpx + (size_t)i * C_DIM * K3C,
                                           nullptr, nullptr, nullptr,
                                           part, nullptr, C_DIM, K3C, K3C / 2);
        red_ln_kernel<1><<<ROWS, 256>>>(part, bp + bc, x,
                                        ln2w + bc, ln2b + bc, nullptr, aC);

        mma_gemm<3><<<gF4, 256, G_SMEM>>>(aC, w1x + (size_t)i * F4_DIM * K3C,
                                          b1 + (size_t)i * F4_DIM, nullptr, nullptr,
                                          nullptr, aF, F4_DIM, K3C, K3C);

        mma_gemm<0><<<gCsp, 256, G_SMEM>>>(aF, w2x + (size_t)i * C_DIM * K3F,
                                           nullptr, nullptr, nullptr,
                                           part, nullptr, C_DIM, K3F, K3F / 2);
        if (i < N_LAYER - 1) {
            red_ln_kernel<1><<<ROWS, 256>>>(part, b2 + bc, x,
                                            ln1w + bc + C_DIM, ln1b + bc + C_DIM,
                                            nullptr, aC);
        } else {
            red_ln_kernel<0><<<ROWS, 256>>>(part, b2 + bc, x,
                                            lnfw, lnfb, h, nullptr);
        }
    }

    head_kernel<<<256, 256>>>(h, head_w, (float*)d_out);
}

// round 17
// speedup vs baseline: 3.1599x; 1.0011x over previous
#include <cuda_runtime.h>
#include <cuda_bf16.h>
#include <cstdint>
#include <math.h>

// ---------------------------------------------------------------------------
// Model constants
// ---------------------------------------------------------------------------
#define N_LAYER 4
#define N_HEADS 16
#define C_DIM   1024
#define T_SEQ   1024
#define B_SZ    2
#define ROWS    (B_SZ * T_SEQ)      // 2048
#define F4_DIM  (4 * C_DIM)         // 4096
#define HEAD_D  64
#define VOCABP1 101
#define TRANS   16
#define K3C     (3 * C_DIM)         // 3072
#define K3F     (3 * F4_DIM)        // 12288
#define NQKV    (3 * C_DIM)         // 3072

// ---------------------------------------------------------------------------
// Static device scratch (no allocations allowed)
// ---------------------------------------------------------------------------
__device__ float g_x   [ROWS * C_DIM];
__device__ float g_h   [ROWS * C_DIM];
__device__ float g_qkv [ROWS * NQKV];
__device__ float g_part[2 * ROWS * C_DIM];            // split-K partials

__device__ __nv_bfloat16 g_aexpC[(size_t)ROWS * K3C];
__device__ __nv_bfloat16 g_aexpF[(size_t)ROWS * K3F];

__device__ __nv_bfloat16 g_wqkv[(size_t)N_LAYER * NQKV * K3C];
__device__ __nv_bfloat16 g_wp  [(size_t)N_LAYER * C_DIM * K3C];
__device__ __nv_bfloat16 g_w1  [(size_t)N_LAYER * F4_DIM * K3C];
__device__ __nv_bfloat16 g_w2  [(size_t)N_LAYER * C_DIM * K3F];

// ---------------------------------------------------------------------------
// PTX helpers (sm_80-safe only; ptxas targets plain sm_103)
// ---------------------------------------------------------------------------
__device__ __forceinline__ uint32_t smem_u32(const void* p) {
    uint32_t a;
    asm("{ .reg .u64 t; cvta.to.shared.u64 t, %1; cvt.u32.u64 %0, t; }" : "=r"(a) : "l"(p));
    return a;
}
__device__ __forceinline__ void cp_async16(uint32_t s, const void* g) {
    asm volatile("cp.async.cg.shared.global [%0], [%1], 16;" :: "r"(s), "l"(g));
}
__device__ __forceinline__ void cp_commit() { asm volatile("cp.async.commit_group;"); }
template<int N> __device__ __forceinline__ void cp_wait() {
    asm volatile("cp.async.wait_group %0;" :: "n"(N));
}
__device__ __forceinline__ void ldsm_x4(uint32_t& r0, uint32_t& r1, uint32_t& r2, uint32_t& r3,
                                        uint32_t addr) {
    asm volatile("ldmatrix.sync.aligned.m8n8.x4.shared.b16 {%0,%1,%2,%3}, [%4];"
                 : "=r"(r0), "=r"(r1), "=r"(r2), "=r"(r3) : "r"(addr));
}
__device__ __forceinline__ void mma16816(float* c, const uint32_t* a, uint32_t b0, uint32_t b1) {
    asm volatile("mma.sync.aligned.m16n8k16.row.col.f32.bf16.bf16.f32 "
                 "{%0,%1,%2,%3}, {%4,%5,%6,%7}, {%8,%9}, {%0,%1,%2,%3};"
                 : "+f"(c[0]), "+f"(c[1]), "+f"(c[2]), "+f"(c[3])
                 : "r"(a[0]), "r"(a[1]), "r"(a[2]), "r"(a[3]), "r"(b0), "r"(b1));
}
__device__ __forceinline__ uint32_t swz(int r, int s8) {
    return (uint32_t)(r * 128 + ((s8 ^ (r & 7)) << 4));
}

// ---------------------------------------------------------------------------
// LayerNorm core. EXP=0: fp32 Y. EXP=1: bf16 [hi|lo|hi] into Ye [row][3C]
// ---------------------------------------------------------------------------
template<int EXP>
__device__ __forceinline__ void ln_core(const float v[4], int row, int tid,
                                        const float* __restrict__ w,
                                        const float* __restrict__ b,
                                        float* __restrict__ Y,
                                        __nv_bfloat16* __restrict__ Ye)
{
    __shared__ float red[8];
    float s = v[0] + v[1] + v[2] + v[3];
#pragma unroll
    for (int off = 16; off; off >>= 1) s += __shfl_xor_sync(~0u, s, off);
    if ((tid & 31) == 0) red[tid >> 5] = s;
    __syncthreads();
    float tot = 0.f;
#pragma unroll
    for (int j = 0; j < 8; ++j) tot += red[j];
    const float mu = tot * (1.0f / C_DIM);
    __syncthreads();

    float ss = 0.f;
#pragma unroll
    for (int i = 0; i < 4; ++i) { float d = v[i] - mu; ss += d * d; }
#pragma unroll
    for (int off = 16; off; off >>= 1) ss += __shfl_xor_sync(~0u, ss, off);
    if ((tid & 31) == 0) red[tid >> 5] = ss;
    __syncthreads();
    float tot2 = 0.f;
#pragma unroll
    for (int j = 0; j < 8; ++j) tot2 += red[j];
    const float rs = rsqrtf(tot2 * (1.0f / C_DIM) + 1e-5f);

#pragma unroll
    for (int i = 0; i < 4; ++i) {
        const int c = tid + 256 * i;
        const float o = (v[i] - mu) * rs * w[c] + b[c];
        if (EXP == 0) {
            Y[(size_t)row * C_DIM + c] = o;
        } else {
            __nv_bfloat16 hi = __float2bfloat16(o);
            __nv_bfloat16 lo = __float2bfloat16(o - __bfloat162float(hi));
            __nv_bfloat16* yr = Ye + (size_t)row * K3C;
            yr[c]             = hi;
            yr[C_DIM + c]     = lo;
            yr[2 * C_DIM + c] = hi;
        }
    }
}

// ---------------------------------------------------------------------------
// Fused embedding + layer-0 ln1
// ---------------------------------------------------------------------------
__global__ void embed_ln_kernel(const int* __restrict__ tokens,
                                const float* __restrict__ tok_emb,
                                const float* __restrict__ pos_emb,
                                const float* __restrict__ w,
                                const float* __restrict__ b,
                                float* __restrict__ X,
                                __nv_bfloat16* __restrict__ Ye)
{
    const int row = blockIdx.x;
    const int tid = threadIdx.x;
    const int t   = row & 1023;
    const int tok = tokens[row];
    float v[4];
#pragma unroll
    for (int i = 0; i < 4; ++i) {
        const int c = tid + 256 * i;
        const float o = tok_emb[(size_t)tok * C_DIM + c] + pos_emb[(size_t)t * C_DIM + c];
        X[(size_t)row * C_DIM + c] = o;
        v[i] = o;
    }
    ln_core<1>(v, row, tid, w, b, nullptr, Ye);
}

// ---------------------------------------------------------------------------
// Fused split-K reduce + residual update + LayerNorm
// ---------------------------------------------------------------------------
template<int EXP>
__global__ void red_ln_kernel(const float* __restrict__ P,
                              const float* __restrict__ bias,
                              float* __restrict__ X,
                              const float* __restrict__ w,
                              const float* __restrict__ b,
                              float* __restrict__ Y, __nv_bfloat16* __restrict__ Ye)
{
    const int row = blockIdx.x;
    const int tid = threadIdx.x;
    const size_t base = (size_t)row * C_DIM;
    float v[4];
#pragma unroll
    for (int i = 0; i < 4; ++i) {
        const int c = tid + 256 * i;
        const float t = X[base + c] + P[base + c] + P[ROWS * C_DIM + base + c] + bias[c];
        X[base + c] = t;
        v[i] = t;
    }
    ln_core<EXP>(v, row, tid, w, b, Y, Ye);
}

// ---------------------------------------------------------------------------
// Weight expansion kernels
// ---------------------------------------------------------------------------
__global__ void expand_wT(const float* __restrict__ W, __nv_bfloat16* __restrict__ out,
                          int K, int N, size_t wstride, size_t ostride)
{
    W   += (size_t)blockIdx.z * wstride;
    out += (size_t)blockIdx.z * ostride;
    __shared__ float t[32][33];
    const int k0 = blockIdx.x * 32, n0 = blockIdx.y * 32;
    const int tx = threadIdx.x, ty = threadIdx.y;
#pragma unroll
    for (int i = 0; i < 4; ++i)
        t[ty + 8 * i][tx] = W[(size_t)(k0 + ty + 8 * i) * N + n0 + tx];
    __syncthreads();
#pragma unroll
    for (int i = 0; i < 4; ++i) {
        int n = n0 + ty + 8 * i;
        int k = k0 + tx;
        float x = t[tx][ty + 8 * i];
        __nv_bfloat16 hi = __float2bfloat16(x);
        __nv_bfloat16 lo = __float2bfloat16(x - __bfloat162float(hi));
        size_t base = (size_t)n * 3 * K;
        out[base + k]         = hi;
        out[base + K + k]     = hi;
        out[base + 2 * K + k] = lo;
    }
}

__global__ void expand_qkv(const float* __restrict__ Wq, const float* __restrict__ Wk,
                           const float* __restrict__ Wv, __nv_bfloat16* __restrict__ out)
{
    const int mat   = blockIdx.z % 3;
    const int layer = blockIdx.z / 3;
    const float* W = (mat == 0) ? Wq : (mat == 1) ? Wk : Wv;
    W   += (size_t)layer * C_DIM * C_DIM;
    out += (size_t)layer * NQKV * K3C + (size_t)mat * C_DIM * K3C;

    __shared__ float t[32][33];
    const int k0 = blockIdx.x * 32, n0 = blockIdx.y * 32;
    const int tx = threadIdx.x, ty = threadIdx.y;
#pragma unroll
    for (int i = 0; i < 4; ++i)
        t[ty + 8 * i][tx] = W[(size_t)(k0 + ty + 8 * i) * C_DIM + n0 + tx];
    __syncthreads();
#pragma unroll
    for (int i = 0; i < 4; ++i) {
        int n = n0 + ty + 8 * i;
        int k = k0 + tx;
        float x = t[tx][ty + 8 * i];
        __nv_bfloat16 hi = __float2bfloat16(x);
        __nv_bfloat16 lo = __float2bfloat16(x - __bfloat162float(hi));
        size_t base = (size_t)n * K3C;
        out[base + k]             = hi;
        out[base + C_DIM + k]     = hi;
        out[base + 2 * C_DIM + k] = lo;
    }
}

// ---------------------------------------------------------------------------
// HMMA bf16 GEMM (unchanged, validated)
// ---------------------------------------------------------------------------
#define G_STAGES 3
#define G_TILEB  (128 * 128)
#define G_STAGEB (2 * G_TILEB)
#define G_SMEM   (G_STAGES * G_STAGEB)   // 98304

template<int EPI>
__global__ __launch_bounds__(256, 2)
void mma_gemm(const __nv_bfloat16* __restrict__ A, const __nv_bfloat16* __restrict__ B,
              const float* __restrict__ bias, const float* __restrict__ biasK,
              const float* __restrict__ biasV,
              float* __restrict__ Cf, __nv_bfloat16* __restrict__ Ce,
              int N, int Kfull, int Ksub)
{
    extern __shared__ char smem[];
    const uint32_t sbase = smem_u32(smem);
    const int tid  = threadIdx.x;
    const int wid  = tid >> 5, lane = tid & 31;
    const int warp_m = wid >> 2, warp_n = wid & 3;
    const int bx = blockIdx.x, by = blockIdx.y, bz = blockIdx.z;

    const char* Abase = (const char*)(A + (size_t)(by * 128) * Kfull + (size_t)bz * Ksub);
    const char* Bbase = (const char*)(B + (size_t)(bx * 128) * Kfull + (size_t)bz * Ksub);
    const size_t ldg = (size_t)Kfull * 2;
    const int nchunks = Ksub >> 6;

    const int r_cp[4] = { tid >> 3, (tid + 256) >> 3, (tid + 512) >> 3, (tid + 768) >> 3 };
    const int s8_cp   = tid & 7;

#pragma unroll
    for (int st = 0; st < G_STAGES - 1; ++st) {
        const uint32_t sb = sbase + st * G_STAGEB;
#pragma unroll
        for (int p = 0; p < 4; ++p) {
            const int r = r_cp[p];
            cp_async16(sb + swz(r, s8_cp),           Abase + (size_t)r * ldg + st * 128 + s8_cp * 16);
            cp_async16(sb + G_TILEB + swz(r, s8_cp), Bbase + (size_t)r * ldg + st * 128 + s8_cp * 16);
        }
        cp_commit();
    }

    float acc[4][4][4];
#pragma unroll
    for (int i = 0; i < 4; ++i)
#pragma unroll
        for (int j = 0; j < 4; ++j)
#pragma unroll
            for (int r = 0; r < 4; ++r) acc[i][j][r] = 0.f;

    const int a_r0 = warp_m * 64 + (lane & 15);
    const int a_s0 = lane >> 4;
    const int b_r0 = warp_n * 32 + (lane & 7) + ((lane >> 4) << 3);
    const int b_s0 = (lane >> 3) & 1;

    for (int c = 0; c < nchunks; ++c) {
        cp_wait<G_STAGES - 2>();
        __syncthreads();

        const int nc = c + G_STAGES - 1;
        if (nc < nchunks) {
            const uint32_t nb = sbase + (nc % G_STAGES) * G_STAGEB;
#pragma unroll
            for (int p = 0; p < 4; ++p) {
                const int r = r_cp[p];
                cp_async16(nb + swz(r, s8_cp),           Abase + (size_t)r * ldg + nc * 128 + s8_cp * 16);
                cp_async16(nb + G_TILEB + swz(r, s8_cp), Bbase + (size_t)r * ldg + nc * 128 + s8_cp * 16);
            }
        }
        cp_commit();

        const uint32_t sb = sbase + (c % G_STAGES) * G_STAGEB;
#pragma unroll
        for (int ks = 0; ks < 4; ++ks) {
            uint32_t af[4][4], bfr[2][4];
#pragma unroll
            for (int ma = 0; ma < 4; ++ma) {
                const int r = a_r0 + ma * 16;
                ldsm_x4(af[ma][0], af[ma][1], af[ma][2], af[ma][3],
                        sb + swz(r, ks * 2 + a_s0));
            }
#pragma unroll
            for (int j = 0; j < 2; ++j) {
                const int r = b_r0 + j * 16;
                ldsm_x4(bfr[j][0], bfr[j][1], bfr[j][2], bfr[j][3],
                        sb + G_TILEB + swz(r, ks * 2 + b_s0));
            }
#pragma unroll
            for (int ma = 0; ma < 4; ++ma)
#pragma unroll
                for (int na = 0; na < 4; ++na)
                    mma16816(acc[ma][na], af[ma], bfr[na >> 1][(na & 1) * 2],
                             bfr[na >> 1][(na & 1) * 2 + 1]);
        }
    }

    float* Cout = (EPI == 0) ? (Cf + (size_t)bz * ROWS * N) : Cf;
#pragma unroll
    for (int ma = 0; ma < 4; ++ma) {
        const int row0 = by * 128 + warp_m * 64 + ma * 16 + (lane >> 2);
        const int row1 = row0 + 8;
#pragma unroll
        for (int na = 0; na < 4; ++na) {
            const int col = bx * 128 + warp_n * 32 + na * 8 + (lane & 3) * 2;
            if (EPI == 0) {
                *reinterpret_cast<float2*>(Cout + (size_t)row0 * N + col) =
                    make_float2(acc[ma][na][0], acc[ma][na][1]);
                *reinterpret_cast<float2*>(Cout + (size_t)row1 * N + col) =
                    make_float2(acc[ma][na][2], acc[ma][na][3]);
                continue;
            }
            float b0, b1;
            if (EPI == 4) {
                b0 = (col < C_DIM) ? bias[col]
                   : (col < 2 * C_DIM) ? biasK[col - C_DIM] : biasV[col - 2 * C_DIM];
                b1 = (col + 1 < C_DIM) ? bias[col + 1]
                   : (col + 1 < 2 * C_DIM) ? biasK[col + 1 - C_DIM] : biasV[col + 1 - 2 * C_DIM];
            } else {
                b0 = bias[col]; b1 = bias[col + 1];
            }
            float v0 = acc[ma][na][0] + b0;
            float v1 = acc[ma][na][1] + b1;
            float v2 = acc[ma][na][2] + b0;
            float v3 = acc[ma][na][3] + b1;
            if (EPI == 3) {
                v0 = 0.5f * v0 * (1.0f + erff(v0 * 0.70710678118654752f));
                v1 = 0.5f * v1 * (1.0f + erff(v1 * 0.70710678118654752f));
                v2 = 0.5f * v2 * (1.0f + erff(v2 * 0.70710678118654752f));
                v3 = 0.5f * v3 * (1.0f + erff(v3 * 0.70710678118654752f));
                __nv_bfloat162 h0, l0, h1, l1;
                h0.x = __float2bfloat16(v0); h0.y = __float2bfloat16(v1);
                l0.x = __float2bfloat16(v0 - __bfloat162float(h0.x));
                l0.y = __float2bfloat16(v1 - __bfloat162float(h0.y));
                h1.x = __float2bfloat16(v2); h1.y = __float2bfloat16(v3);
                l1.x = __float2bfloat16(v2 - __bfloat162float(h1.x));
                l1.y = __float2bfloat16(v3 - __bfloat162float(h1.y));
                __nv_bfloat16* c0 = Ce + (size_t)row0 * 3 * N;
                __nv_bfloat16* c1 = Ce + (size_t)row1 * 3 * N;
                *reinterpret_cast<__nv_bfloat162*>(c0 + col)         = h0;
                *reinterpret_cast<__nv_bfloat162*>(c0 + N + col)     = l0;
                *reinterpret_cast<__nv_bfloat162*>(c0 + 2 * N + col) = h0;
                *reinterpret_cast<__nv_bfloat162*>(c1 + col)         = h1;
                *reinterpret_cast<__nv_bfloat162*>(c1 + N + col)     = l1;
                *reinterpret_cast<__nv_bfloat162*>(c1 + 2 * N + col) = h1;
            } else {
                *reinterpret_cast<float2*>(Cout + (size_t)row0 * N + col) = make_float2(v0, v1);
                *reinterpret_cast<float2*>(Cout + (size_t)row1 * N + col) = make_float2(v2, v3);
            }
        }
    }
}

// ---------------------------------------------------------------------------
// MMA flash attention v2: 128-query tile, 512 threads (16 warps = 4m x 4n).
// Same fragment layouts as v1 (validated); K/V tile conversions amortized
// over 2x queries. SMEM: Qh 0(16K), Ql 16K, Kh 32K(8K), Kl 40K, Vth 48K,
// Vtl 56K, Ph 64K(16K), Pl 80K, stats @96K. Total 100352 -> 102400.
// ---------------------------------------------------------------------------
#define ATT_SMEM 102400

__global__ __launch_bounds__(512, 1)
void attn_mma(const float* __restrict__ QKV, __nv_bfloat16* __restrict__ Ye)
{
    extern __shared__ char sm[];
    const uint32_t sb = smem_u32(sm);
    const uint32_t QHo = 0, QLo = 16384, KHo = 32768, KLo = 40960,
                   VHo = 49152, VLo = 57344, PHo = 65536, PLo = 81920;
    float* m_row = (float*)(sm + 98304);   // 128
    float* l_row = (float*)(sm + 98816);   // 128
    float* crw   = (float*)(sm + 99328);   // 128
    float* wred  = (float*)(sm + 99840);   // [4][128]

    const int bh = blockIdx.x, b = bh >> 4, h = bh & 15;
    const int qt = (int)gridDim.y - 1 - (int)blockIdx.y;   // heavy tiles first
    const int q0 = qt * 128;
    const int tid = threadIdx.x, lane = tid & 31, wid = tid >> 5;
    const int warp_m = wid >> 2, warp_n = wid & 3;         // 4m x 4n
    const int r_q = lane >> 2, cq = lane & 3;

    // load Q tile (scale folded), split hi/lo, swizzled row-major [query][dim]
    for (int idx = tid; idx < 128 * 64; idx += 512) {
        const int r = idx >> 6, d = idx & 63;
        const float q = QKV[(size_t)(b * T_SEQ + q0 + r) * NQKV + h * HEAD_D + d] * 0.125f;
        const __nv_bfloat16 hi = __float2bfloat16(q);
        const __nv_bfloat16 lo = __float2bfloat16(q - __bfloat162float(hi));
        const uint32_t off = swz(r, d >> 3) + (d & 7) * 2;
        *(__nv_bfloat16*)(sm + QHo + off) = hi;
        *(__nv_bfloat16*)(sm + QLo + off) = lo;
    }
    if (tid < 128) { m_row[tid] = -INFINITY; l_row[tid] = 0.f; }

    float of[2][2][4];
#pragma unroll
    for (int i = 0; i < 2; ++i)
#pragma unroll
        for (int j = 0; j < 2; ++j)
#pragma unroll
            for (int e = 0; e < 4; ++e) of[i][j][e] = 0.f;

    const int ktmax = 2 * qt + 1;
    for (int kt = 0; kt <= ktmax; ++kt) {
        const int k0 = kt * 64;
        __syncthreads();
        // load K (keys x dims) and V (TRANSPOSED dims x keys), hi/lo split
        for (int idx = tid; idx < 64 * 64; idx += 512) {
            const int r = idx >> 6, d = idx & 63;
            const size_t g = (size_t)(b * T_SEQ + k0 + r) * NQKV + h * HEAD_D + d;
            const float kv = QKV[g + C_DIM];
            const float vv = QKV[g + 2 * C_DIM];
            const __nv_bfloat16 khi = __float2bfloat16(kv);
            const __nv_bfloat16 klo = __float2bfloat16(kv - __bfloat162float(khi));
            const uint32_t koff = swz(r, d >> 3) + (d & 7) * 2;
            *(__nv_bfloat16*)(sm + KHo + koff) = khi;
            *(__nv_bfloat16*)(sm + KLo + koff) = klo;
            const __nv_bfloat16 vhi = __float2bfloat16(vv);
            const __nv_bfloat16 vlo = __float2bfloat16(vv - __bfloat162float(vhi));
            const uint32_t voff = swz(d, r >> 3) + (r & 7) * 2;
            *(__nv_bfloat16*)(sm + VHo + voff) = vhi;
            *(__nv_bfloat16*)(sm + VLo + voff) = vlo;
        }
        __syncthreads();

        // ---- S = Q K^T (3-term split) ----
        float sf[2][2][4];
#pragma unroll
        for (int i = 0; i < 2; ++i)
#pragma unroll
            for (int j = 0; j < 2; ++j)
#pragma unroll
                for (int e = 0; e < 4; ++e) sf[i][j][e] = 0.f;
#pragma unroll
        for (int p = 0; p < 3; ++p) {
            const uint32_t Ab = sb + ((p == 1) ? QLo : QHo);
            const uint32_t Bb = sb + ((p == 2) ? KLo : KHo);
#pragma unroll
            for (int ks = 0; ks < 4; ++ks) {
                uint32_t af[2][4], bf4[4];
#pragma unroll
                for (int ma = 0; ma < 2; ++ma)
                    ldsm_x4(af[ma][0], af[ma][1], af[ma][2], af[ma][3],
                            Ab + swz(warp_m * 32 + ma * 16 + (lane & 15), ks * 2 + (lane >> 4)));
                ldsm_x4(bf4[0], bf4[1], bf4[2], bf4[3],
                        Bb + swz(warp_n * 16 + (lane & 7) + ((lane >> 4) << 3),
                                 ks * 2 + ((lane >> 3) & 1)));
#pragma unroll
                for (int ma = 0; ma < 2; ++ma)
#pragma unroll
                    for (int na = 0; na < 2; ++na)
                        mma16816(sf[ma][na], af[ma], bf4[na * 2], bf4[na * 2 + 1]);
            }
        }

        // ---- mask + row max ----
        float rmax[2][2] = { {-INFINITY, -INFINITY}, {-INFINITY, -INFINITY} };
#pragma unroll
        for (int ma = 0; ma < 2; ++ma)
#pragma unroll
            for (int na = 0; na < 2; ++na)
#pragma unroll
                for (int e = 0; e < 4; ++e) {
                    const int row_l = warp_m * 32 + ma * 16 + r_q + (e >> 1) * 8;
                    const int key   = k0 + warp_n * 16 + na * 8 + cq * 2 + (e & 1);
                    const bool valid = (key <= q0 + row_l) && ((key & 15) != 15);
                    const float v = valid ? sf[ma][na][e] : -INFINITY;
                    sf[ma][na][e] = v;
                    rmax[ma][e >> 1] = fmaxf(rmax[ma][e >> 1], v);
                }
#pragma unroll
        for (int ma = 0; ma < 2; ++ma)
#pragma unroll
            for (int hf = 0; hf < 2; ++hf) {
                float v = rmax[ma][hf];
                v = fmaxf(v, __shfl_xor_sync(~0u, v, 1));
                v = fmaxf(v, __shfl_xor_sync(~0u, v, 2));
                rmax[ma][hf] = v;
            }
        if (cq == 0) {
#pragma unroll
            for (int ma = 0; ma < 2; ++ma)
#pragma unroll
                for (int hf = 0; hf < 2; ++hf)
                    wred[warp_n * 128 + warp_m * 32 + ma * 16 + r_q + hf * 8] = rmax[ma][hf];
        }
        __syncthreads();
        if (tid < 128) {
            const float mo = m_row[tid];
            float mn = fmaxf(fmaxf(wred[tid], wred[128 + tid]),
                             fmaxf(wred[256 + tid], wred[384 + tid]));
            mn = fmaxf(mn, mo);
            const float c = __expf(mo - mn);
            crw[tid] = c;
            m_row[tid] = mn;
            l_row[tid] *= c;
        }
        __syncthreads();

        // ---- P = exp(S - m); write Ph/Pl; scale O; row sums ----
        float m4[2][2], c4[2][2];
#pragma unroll
        for (int ma = 0; ma < 2; ++ma)
#pragma unroll
            for (int hf = 0; hf < 2; ++hf) {
                const int row_l = warp_m * 32 + ma * 16 + r_q + hf * 8;
                m4[ma][hf] = m_row[row_l];
                c4[ma][hf] = crw[row_l];
            }
        float rs[2][2] = { {0.f, 0.f}, {0.f, 0.f} };
#pragma unroll
        for (int ma = 0; ma < 2; ++ma)
#pragma unroll
            for (int na = 0; na < 2; ++na) {
                const float p0 = __expf(sf[ma][na][0] - m4[ma][0]);
                const float p1 = __expf(sf[ma][na][1] - m4[ma][0]);
                const float p2 = __expf(sf[ma][na][2] - m4[ma][1]);
                const float p3 = __expf(sf[ma][na][3] - m4[ma][1]);
                rs[ma][0] += p0 + p1;
                rs[ma][1] += p2 + p3;
                const int colb = warp_n * 16 + na * 8 + cq * 2;
                const int row0 = warp_m * 32 + ma * 16 + r_q;
                const uint32_t o0 = swz(row0, colb >> 3) + (colb & 7) * 2;
                const uint32_t o1 = swz(row0 + 8, colb >> 3) + (colb & 7) * 2;
                __nv_bfloat162 h2, l2;
                h2.x = __float2bfloat16(p0); h2.y = __float2bfloat16(p1);
                l2.x = __float2bfloat16(p0 - __bfloat162float(h2.x));
                l2.y = __float2bfloat16(p1 - __bfloat162float(h2.y));
                *(__nv_bfloat162*)(sm + PHo + o0) = h2;
                *(__nv_bfloat162*)(sm + PLo + o0) = l2;
                h2.x = __float2bfloat16(p2); h2.y = __float2bfloat16(p3);
                l2.x = __float2bfloat16(p2 - __bfloat162float(h2.x));
                l2.y = __float2bfloat16(p3 - __bfloat162float(h2.y));
                *(__nv_bfloat162*)(sm + PHo + o1) = h2;
                *(__nv_bfloat162*)(sm + PLo + o1) = l2;
                of[ma][na][0] *= c4[ma][0];
                of[ma][na][1] *= c4[ma][0];
                of[ma][na][2] *= c4[ma][1];
                of[ma][na][3] *= c4[ma][1];
            }
#pragma unroll
        for (int ma = 0; ma < 2; ++ma)
#pragma unroll
            for (int hf = 0; hf < 2; ++hf) {
                float v = rs[ma][hf];
                v += __shfl_xor_sync(~0u, v, 1);
                v += __shfl_xor_sync(~0u, v, 2);
                rs[ma][hf] = v;
            }
        if (cq == 0) {
#pragma unroll
            for (int ma = 0; ma < 2; ++ma)
#pragma unroll
                for (int hf = 0; hf < 2; ++hf)
                    wred[warp_n * 128 + warp_m * 32 + ma * 16 + r_q + hf * 8] = rs[ma][hf];
        }
        __syncthreads();
        if (tid < 128)
            l_row[tid] += wred[tid] + wred[128 + tid] + wred[256 + tid] + wred[384 + tid];

        // ---- O += P V (3-term split); B = V^T (dims x keys) ----
#pragma unroll
        for (int p = 0; p < 3; ++p) {
            const uint32_t Ab = sb + ((p == 1) ? PLo : PHo);
            const uint32_t Bb = sb + ((p == 2) ? VLo : VHo);
#pragma unroll
            for (int ks = 0; ks < 4; ++ks) {
                uint32_t af[2][4], bf4[4];
#pragma unroll
                for (int ma = 0; ma < 2; ++ma)
                    ldsm_x4(af[ma][0], af[ma][1], af[ma][2], af[ma][3],
                            Ab + swz(warp_m * 32 + ma * 16 + (lane & 15), ks * 2 + (lane >> 4)));
                ldsm_x4(bf4[0], bf4[1], bf4[2], bf4[3],
                        Bb + swz(warp_n * 16 + (lane & 7) + ((lane >> 4) << 3),
                                 ks * 2 + ((lane >> 3) & 1)));
#pragma unroll
                for (int ma = 0; ma < 2; ++ma)
#pragma unroll
                    for (int na = 0; na < 2; ++na)
                        mma16816(of[ma][na], af[ma], bf4[na * 2], bf4[na * 2 + 1]);
            }
        }
    }

    // ---- finalize: O /= l; write expanded bf16 [hi|lo|hi] ----
    __syncthreads();
    if (tid < 128) crw[tid] = 1.0f / l_row[tid];
    __syncthreads();
    float i4[2][2];
#pragma unroll
    for (int ma = 0; ma < 2; ++ma)
#pragma unroll
        for (int hf = 0; hf < 2; ++hf)
            i4[ma][hf] = crw[warp_m * 32 + ma * 16 + r_q + hf * 8];
#pragma unroll
    for (int ma = 0; ma < 2; ++ma)
#pragma unroll
        for (int na = 0; na < 2; ++na) {
            const int row0 = warp_m * 32 + ma * 16 + r_q;
            const int col  = h * HEAD_D + warp_n * 16 + na * 8 + cq * 2;
#pragma unroll
            for (int hf = 0; hf < 2; ++hf) {
                const float v0 = of[ma][na][hf * 2]     * i4[ma][hf];
                const float v1 = of[ma][na][hf * 2 + 1] * i4[ma][hf];
                __nv_bfloat162 hi2, lo2;
                hi2.x = __float2bfloat16(v0); hi2.y = __float2bfloat16(v1);
                lo2.x = __float2bfloat16(v0 - __bfloat162float(hi2.x));
                lo2.y = __float2bfloat16(v1 - __bfloat162float(hi2.y));
                __nv_bfloat16* yr = Ye + (size_t)(b * T_SEQ + q0 + row0 + hf * 8) * K3C;
                *reinterpret_cast<__nv_bfloat162*>(yr + col)             = hi2;
                *reinterpret_cast<__nv_bfloat162*>(yr + C_DIM + col)     = lo2;
                *reinterpret_cast<__nv_bfloat162*>(yr + 2 * C_DIM + col) = hi2;
            }
        }
}

// ---------------------------------------------------------------------------
// EinLinear head
// ---------------------------------------------------------------------------
__global__ __launch_bounds__(256)
void head_kernel(const float* __restrict__ X, const float* __restrict__ Wh,
                 float* __restrict__ out)
{
    const int e     = blockIdx.x & 15;
    const int chunk = blockIdx.x >> 4;
    const int tid = threadIdx.x;
    const int warp = tid >> 5, lane = tid & 31;

    __shared__ float xs[8][C_DIM];
    int rows[8];
#pragma unroll
    for (int j = 0; j < 8; ++j) rows[j] = (chunk * 8 + j) * TRANS + e;

#pragma unroll
    for (int j = 0; j < 8; ++j)
        for (int idx = tid; idx < C_DIM; idx += 256)
            xs[j][idx] = X[(size_t)rows[j] * C_DIM + idx];
    __syncthreads();

    for (int o = warp; o < VOCABP1; o += 8) {
        const float* w = Wh + ((size_t)e * VOCABP1 + o) * C_DIM;
        float a[8];
#pragma unroll
        for (int j = 0; j < 8; ++j) a[j] = 0.f;
        for (int k = lane; k < C_DIM; k += 32) {
            const float wv = w[k];
#pragma unroll
            for (int j = 0; j < 8; ++j) a[j] += wv * xs[j][k];
        }
#pragma unroll
        for (int j = 0; j < 8; ++j)
#pragma unroll
            for (int off = 16; off; off >>= 1)
                a[j] += __shfl_xor_sync(~0u, a[j], off);
        if (lane == 0) {
#pragma unroll
            for (int j = 0; j < 8; ++j)
                out[(size_t)rows[j] * VOCABP1 + o] = a[j];
        }
    }
}

// ---------------------------------------------------------------------------
// Launch. Order: expand_qkv(1), embed_ln(2), QKV GEMM(3), attn_mma(4) <- ncu.
// ---------------------------------------------------------------------------
extern "C" void kernel_launch(void* const* d_in, const int* in_sizes, int n_in,
                              void* d_out, int out_size)
{
    const int*   tokens  = (const int*)  d_in[0];
    const float* tok_emb = (const float*)d_in[1];
    const float* pos_emb = (const float*)d_in[2];
    const float* Wq = (const float*)d_in[3];  const float* bq = (const float*)d_in[4];
    const float* Wk = (const float*)d_in[5];  const float* bk = (const float*)d_in[6];
    const float* Wv = (const float*)d_in[7];  const float* bv = (const float*)d_in[8];
    const float* Wp = (const float*)d_in[9];  const float* bp = (const float*)d_in[10];
    const float* ln1w = (const float*)d_in[11]; const float* ln1b = (const float*)d_in[12];
    const float* ln2w = (const float*)d_in[13]; const float* ln2b = (const float*)d_in[14];
    const float* W1 = (const float*)d_in[15]; const float* b1 = (const float*)d_in[16];
    const float* W2 = (const float*)d_in[17]; const float* b2 = (const float*)d_in[18];
    const float* lnfw = (const float*)d_in[19]; const float* lnfb = (const float*)d_in[20];
    const float* head_w = (const float*)d_in[21];

    float *x, *h, *qkv, *part;
    __nv_bfloat16 *aC, *aF, *wqkvx, *wpx, *w1x, *w2x;
    cudaGetSymbolAddress((void**)&x,    g_x);
    cudaGetSymbolAddress((void**)&h,    g_h);
    cudaGetSymbolAddress((void**)&qkv,  g_qkv);
    cudaGetSymbolAddress((void**)&part, g_part);
    cudaGetSymbolAddress((void**)&aC,   g_aexpC);
    cudaGetSymbolAddress((void**)&aF,   g_aexpF);
    cudaGetSymbolAddress((void**)&wqkvx, g_wqkv);
    cudaGetSymbolAddress((void**)&wpx,  g_wp);
    cudaGetSymbolAddress((void**)&w1x,  g_w1);
    cudaGetSymbolAddress((void**)&w2x,  g_w2);

    cudaFuncSetAttribute(mma_gemm<0>, cudaFuncAttributeMaxDynamicSharedMemorySize, G_SMEM);
    cudaFuncSetAttribute(mma_gemm<3>, cudaFuncAttributeMaxDynamicSharedMemorySize, G_SMEM);
    cudaFuncSetAttribute(mma_gemm<4>, cudaFuncAttributeMaxDynamicSharedMemorySize, G_SMEM);
    cudaFuncSetAttribute(attn_mma,   cudaFuncAttributeMaxDynamicSharedMemorySize, ATT_SMEM);

    const dim3 wb(32, 8);
    const dim3 gQKV(NQKV   / 128, ROWS / 128);        // (24, 16)
    const dim3 gF4 (F4_DIM / 128, ROWS / 128);        // (32, 16)
    const dim3 gCsp(C_DIM  / 128, ROWS / 128, 2);     // (8, 16, 2) split-K
    const dim3 gAtt(B_SZ * N_HEADS, T_SEQ / 128);     // (32, 8)

    // 1: all Q/K/V weight expansions
    expand_qkv<<<dim3(32, 32, 3 * N_LAYER), wb>>>(Wq, Wk, Wv, wqkvx);
    // 2: fused embedding + layer-0 ln1
    embed_ln_kernel<<<ROWS, 256>>>(tokens, tok_emb, pos_emb, ln1w, ln1b, x, aC);
    // 3: layer-0 QKV GEMM
    mma_gemm<4><<<gQKV, 256, G_SMEM>>>(aC, wqkvx, bq, bk, bv,
                                       qkv, nullptr, NQKV, K3C, K3C);
    // 4: layer-0 attention (MMA, 128q)  <-- ncu profiles our 4th launch
    attn_mma<<<gAtt, 512, ATT_SMEM>>>(qkv, aC);

    // remaining weight expansions
    expand_wT<<<dim3(32, 32, N_LAYER), wb>>>(Wp, wpx,
        C_DIM, C_DIM, (size_t)C_DIM * C_DIM, (size_t)C_DIM * K3C);
    expand_wT<<<dim3(32, 128, N_LAYER), wb>>>(W1, w1x,
        C_DIM, F4_DIM, (size_t)C_DIM * F4_DIM, (size_t)F4_DIM * K3C);
    expand_wT<<<dim3(128, 32, N_LAYER), wb>>>(W2, w2x,
        F4_DIM, C_DIM, (size_t)F4_DIM * C_DIM, (size_t)C_DIM * K3F);

    for (int i = 0; i < N_LAYER; ++i) {
        const size_t bc = (size_t)i * C_DIM;

        if (i > 0) {
            mma_gemm<4><<<gQKV, 256, G_SMEM>>>(aC, wqkvx + (size_t)i * NQKV * K3C,
                                               bq + bc, bk + bc, bv + bc,
                                               qkv, nullptr, NQKV, K3C, K3C);
            attn_mma<<<gAtt, 512, ATT_SMEM>>>(qkv, aC);
        }

        mma_gemm<0><<<gCsp, 256, G_SMEM>>>(aC, wpx + (size_t)i * C_DIM * K3C,
                                           nullptr, nullptr, nullptr,
                                           part, nullptr, C_DIM, K3C, K3C / 2);
        red_ln_kernel<1><<<ROWS, 256>>>(part, bp + bc, x,
                                        ln2w + bc, ln2b + bc, nullptr, aC);

        mma_gemm<3><<<gF4, 256, G_SMEM>>>(aC, w1x + (size_t)i * F4_DIM * K3C,
                                          b1 + (size_t)i * F4_DIM, nullptr, nullptr,
                                          nullptr, aF, F4_DIM, K3C, K3C);

        mma_gemm<0><<<gCsp, 256, G_SMEM>>>(aF, w2x + (size_t)i * C_DIM * K3F,
                                           nullptr, nullptr, nullptr,
                                           part, nullptr, C_DIM, K3F, K3F / 2);
        if (i < N_LAYER - 1) {
            red_ln_kernel<1><<<ROWS, 256>>>(part, b2 + bc, x,
                                            ln1w + bc + C_DIM, ln1b + bc + C_DIM,
                                            nullptr, aC);
        } else {
            red_ln_kernel<0><<<ROWS, 256>>>(part, b2 + bc, x,
                                            lnfw, lnfb, h, nullptr);
        }
    }

    head_kernel<<<256, 256>>>(h, head_w, (float*)d_out);
}